// round 10
// baseline (speedup 1.0000x reference)
#include <cuda_runtime.h>

#define NNODE  128
#define NEDGE  1024
#define ETOT   1152
#define HFEAT  128
#define NGRAPH 1024
#define NTHREADS 512

// ---------------------------------------------------------------------------
// Device-global setup state (rebuilt every launch; deterministic).
// ---------------------------------------------------------------------------
__device__ int   g_csr_ptr[NNODE + 1];
__device__ int   g_csr_src[ETOT];
__device__ float g_t[HFEAT];                 // sorted relu breakpoints
__device__ float g_A[(HFEAT + 1) * HFEAT];   // interval slopes   (129 x 128)
__device__ float g_B[(HFEAT + 1) * HFEAT];   // interval offsets  (129 x 128)

// ---------------------------------------------------------------------------
// Combined setup: block 0 = CSR (warp-match stable ranks), block 1 = PWL.
// ---------------------------------------------------------------------------
__global__ void setup_kernel(const int* __restrict__ ei,
                             const float* __restrict__ w_in,
                             const float* __restrict__ b_in,
                             const float* __restrict__ W) {
    if (blockIdx.x == 0) {
        __shared__ int s_src[NEDGE];
        __shared__ int s_dst[NEDGE];
        __shared__ int hist[32][NNODE];
        __shared__ int cnt[NNODE];
        __shared__ int base[NNODE + 1];
        const int t = threadIdx.x;
        const int w = t >> 5, l = t & 31;
        s_src[t] = ei[t];
        s_dst[t] = ei[NEDGE + t];
        for (int i = t; i < 32 * NNODE; i += 1024) ((int*)hist)[i] = 0;
        __syncthreads();
        const int d = s_dst[t];
        unsigned mask = __match_any_sync(0xffffffffu, d);
        int lane_rank = __popc(mask & ((1u << l) - 1u));
        if (l == (__ffs(mask) - 1)) hist[w][d] = __popc(mask);
        __syncthreads();
        if (t < NNODE) {
            int acc = 0;
#pragma unroll
            for (int c = 0; c < 32; ++c) {
                int v = hist[c][t];
                hist[c][t] = acc;
                acc += v;
            }
            cnt[t] = acc;
        }
        __syncthreads();
        if (t == 0) {
            int acc = 0;
            for (int dd = 0; dd < NNODE; ++dd) { base[dd] = acc; acc += cnt[dd] + 1; }
            base[NNODE] = acc;
        }
        __syncthreads();
        if (t <= NNODE) g_csr_ptr[t] = base[t];
        g_csr_src[base[d] + hist[w][d] + lane_rank] = s_src[t];
        if (t < NNODE) g_csr_src[base[t] + cnt[t]] = t;   // self loop last
    } else {
        __shared__ float sw[HFEAT], sb[HFEAT], st[HFEAT];
        __shared__ int   ord[HFEAT];
        const int t = threadIdx.x;
        if (t >= HFEAT) return;
        sw[t] = w_in[t];
        sb[t] = b_in[t];
        __syncthreads();
        const float wf = sw[t], bf = sb[t];
        const float INF = __int_as_float(0x7f800000);
        float tf = (wf == 0.0f) ? INF : (-bf / wf);
        st[t] = tf;
        __syncthreads();
        tf = st[t];
        int rank = 0;
        for (int g = 0; g < HFEAT; ++g) {
            float tg = st[g];
            rank += (tg < tf) || (tg == tf && g < t);
        }
        ord[rank] = t;
        __syncthreads();
        g_t[t] = st[ord[t]];

        const int c = t;
        float A = 0.0f, B = 0.0f;
        for (int f = 0; f < HFEAT; ++f) {
            float Wfc = W[f * HFEAT + c];
            float w = sw[f];
            if (w < 0.0f)                       { A += w * Wfc; B += sb[f] * Wfc; }
            else if (w == 0.0f && sb[f] > 0.0f) { B += sb[f] * Wfc; }
        }
        g_A[c] = A; g_B[c] = B;
        for (int j = 0; j < HFEAT; ++j) {
            int f = ord[j];
            float w = sw[f];
            float Wfc = W[f * HFEAT + c];
            if (w > 0.0f)      { A += w * Wfc; B += sb[f] * Wfc; }
            else if (w < 0.0f) { A -= w * Wfc; B -= sb[f] * Wfc; }
            g_A[(j + 1) * HFEAT + c] = A;
            g_B[(j + 1) * HFEAT + c] = B;
        }
    }
}

// ---------------------------------------------------------------------------
// Shared memory layout (pitch 128). sW holds g1w all kernel.
// sh doubles as: L0 output (GEMM input) -> pool partials (after GEMM done).
// ---------------------------------------------------------------------------
constexpr int OFF_SH    = 0;
constexpr int OFF_SXH   = OFF_SH  + NNODE * HFEAT;       // 16384
constexpr int OFF_SW    = OFF_SXH + NNODE * HFEAT;       // 16384
constexpr int OFF_SEX   = OFF_SW  + HFEAT * HFEAT;       // 4608
constexpr int OFF_SS    = OFF_SEX + ETOT * 4;            // 512
constexpr int OFF_SD    = OFF_SS  + 512;                 // 512
constexpr int OFF_SATT  = OFF_SD  + 512;                 // 256
constexpr int OFF_SCALE = OFF_SATT + 256;                // 128
constexpr int OFF_BIAS  = OFF_SCALE + 128;               // 128
constexpr int OFF_HP    = OFF_BIAS + 128;                // 128
constexpr int OFF_ZZ    = OFF_HP + 128;                  // 64
constexpr int OFF_XV    = OFF_ZZ + 64;                   // 128
constexpr int OFF_JX    = OFF_XV + 128;                  // 128
constexpr int SM_FLOATS = OFF_JX + 128;
constexpr int SM_INTS   = 132 + ETOT;
constexpr int SMEM_BYTES = SM_FLOATS * 4 + SM_INTS * 4;

// ---------------------------------------------------------------------------
// Packed fp32x2 helpers (f32x2 ops are PTX-only)
// ---------------------------------------------------------------------------
__device__ __forceinline__ unsigned long long pack2(float a) {
    unsigned long long r;
    unsigned int ai = __float_as_uint(a);
    asm("mov.b64 %0, {%1, %1};" : "=l"(r) : "r"(ai));
    return r;
}
__device__ __forceinline__ void ffma2(unsigned long long& d,
                                      unsigned long long a,
                                      unsigned long long b) {
    asm("fma.rn.f32x2 %0, %1, %2, %0;" : "+l"(d) : "l"(a), "l"(b));
}
__device__ __forceinline__ void fadd2(unsigned long long& d,
                                      unsigned long long a) {
    asm("add.rn.f32x2 %0, %0, %1;" : "+l"(d) : "l"(a));
}

// ---------------------------------------------------------------------------
// Split-K GEMM: C = A @ W, all SMEM, 16 warps, 8x8 thread tiles.
// One internal __syncthreads(); all 512 threads must call.
// ---------------------------------------------------------------------------
__device__ __forceinline__ void gemm_sk(const float* __restrict__ A,
                                        const float* __restrict__ sW,
                                        float* __restrict__ C, int tid) {
    const int w  = tid >> 5;
    const int l  = tid & 31;
    const int kh = w >> 3;
    const int r0 = (w & 7) * 16 + (l >> 4) * 8;
    const int ca = (l & 15) * 4;
    const int k0 = kh * 64;

    unsigned long long acc[8][4];
#pragma unroll
    for (int i = 0; i < 8; ++i)
#pragma unroll
        for (int j = 0; j < 4; ++j) acc[i][j] = 0ull;

#pragma unroll 2
    for (int k = k0; k < k0 + 64; k += 2) {
        float2 a[8];
#pragma unroll
        for (int i = 0; i < 8; ++i)
            a[i] = *(const float2*)(A + (r0 + i) * HFEAT + k);
        ulonglong2 w00 = *(const ulonglong2*)(sW + k * HFEAT + ca);
        ulonglong2 w01 = *(const ulonglong2*)(sW + k * HFEAT + ca + 64);
        ulonglong2 w10 = *(const ulonglong2*)(sW + (k + 1) * HFEAT + ca);
        ulonglong2 w11 = *(const ulonglong2*)(sW + (k + 1) * HFEAT + ca + 64);
#pragma unroll
        for (int i = 0; i < 8; ++i) {
            unsigned long long ax = pack2(a[i].x);
            unsigned long long ay = pack2(a[i].y);
            ffma2(acc[i][0], ax, w00.x);
            ffma2(acc[i][1], ax, w00.y);
            ffma2(acc[i][2], ax, w01.x);
            ffma2(acc[i][3], ax, w01.y);
            ffma2(acc[i][0], ay, w10.x);
            ffma2(acc[i][1], ay, w10.y);
            ffma2(acc[i][2], ay, w11.x);
            ffma2(acc[i][3], ay, w11.y);
        }
    }

    if (kh == 1) {
#pragma unroll
        for (int i = 0; i < 8; ++i) {
            ulonglong2 s0, s1;
            s0.x = acc[i][0]; s0.y = acc[i][1];
            s1.x = acc[i][2]; s1.y = acc[i][3];
            *(ulonglong2*)(C + (r0 + i) * HFEAT + ca)      = s0;
            *(ulonglong2*)(C + (r0 + i) * HFEAT + ca + 64) = s1;
        }
    }
    __syncthreads();
    if (kh == 0) {
#pragma unroll
        for (int i = 0; i < 8; ++i) {
            ulonglong2 p0 = *(const ulonglong2*)(C + (r0 + i) * HFEAT + ca);
            ulonglong2 p1 = *(const ulonglong2*)(C + (r0 + i) * HFEAT + ca + 64);
            fadd2(acc[i][0], p0.x);
            fadd2(acc[i][1], p0.y);
            fadd2(acc[i][2], p1.x);
            fadd2(acc[i][3], p1.y);
            ulonglong2 s0, s1;
            s0.x = acc[i][0]; s0.y = acc[i][1];
            s1.x = acc[i][2]; s1.y = acc[i][3];
            *(ulonglong2*)(C + (r0 + i) * HFEAT + ca)      = s0;
            *(ulonglong2*)(C + (r0 + i) * HFEAT + ca + 64) = s1;
        }
    }
}

__global__ __launch_bounds__(NTHREADS, 1)
void gnn_kernel(const float* __restrict__ x,
                const float* __restrict__ g0as, const float* __restrict__ g0ad,
                const float* __restrict__ g0b,
                const float* __restrict__ bn0g, const float* __restrict__ bn0b,
                const float* __restrict__ bn0m, const float* __restrict__ bn0v,
                const float* __restrict__ g1w, const float* __restrict__ g1as,
                const float* __restrict__ g1ad, const float* __restrict__ g1b,
                const float* __restrict__ bn1g, const float* __restrict__ bn1b,
                const float* __restrict__ bn1m, const float* __restrict__ bn1v,
                const float* __restrict__ w1, const float* __restrict__ b1,
                const float* __restrict__ w2, const float* __restrict__ b2,
                float* __restrict__ out) {
    extern __shared__ float smem[];
    float* sh    = smem + OFF_SH;     // L0 output; later: pool partials
    float* sxh   = smem + OFF_SXH;
    float* sW    = smem + OFF_SW;
    float* sex   = smem + OFF_SEX;
    float* s_s   = smem + OFF_SS;
    float* s_d   = smem + OFF_SD;
    float* satt  = smem + OFF_SATT;
    float* sscale= smem + OFF_SCALE;
    float* sbias = smem + OFF_BIAS;
    float* hp    = smem + OFF_HP;
    float* zz    = smem + OFF_ZZ;
    float* sxv   = smem + OFF_XV;
    int*   jidx  = (int*)(smem + OFF_JX);
    int*   sptr  = (int*)(smem + SM_FLOATS);
    int*   scsr  = sptr + 132;

    const int tid  = threadIdx.x;
    const int wid  = tid >> 5;
    const int lane = tid & 31;
    const int b    = blockIdx.x;

    // ---- init ----
    for (int i = tid; i <= NNODE; i += NTHREADS) sptr[i] = g_csr_ptr[i];
    for (int i = tid; i < ETOT; i += NTHREADS)   scsr[i] = g_csr_src[i];
    for (int i = tid; i < HFEAT * HFEAT / 4; i += NTHREADS)
        *(float4*)(sW + i * 4) = *(const float4*)(g1w + i * 4);
    if (tid < 128) {
        satt[tid]       = g0as[tid];
        satt[128 + tid] = g0ad[tid];
        float sc = bn0g[tid] * rsqrtf(bn0v[tid] + 1e-5f);
        sscale[tid] = sc;
        sbias[tid]  = fmaf(g0b[tid] - bn0m[tid], sc, bn0b[tid]);
        float xv = x[b * NNODE + tid];
        sxv[tid] = xv;
        int lo = 0, hi = HFEAT;
        while (lo < hi) {
            int mid = (lo + hi) >> 1;
            if (g_t[mid] <= xv) lo = mid + 1; else hi = mid;
        }
        jidx[tid] = lo;
    }
    __syncthreads();

    // ---- xh0 = x*A_j + B_j (PWL, replaces proj+GEMM0) with fused L0 scores ----
    {
        float4 a1 = *(const float4*)(satt + lane * 4);
        float4 a2 = *(const float4*)(satt + 128 + lane * 4);
        for (int n = wid; n < NNODE; n += 16) {
            int   j  = jidx[n];
            float xv = sxv[n];
            float4 A0 = *(const float4*)(g_A + j * HFEAT + lane * 4);
            float4 B0 = *(const float4*)(g_B + j * HFEAT + lane * 4);
            float4 v;
            v.x = fmaf(xv, A0.x, B0.x);
            v.y = fmaf(xv, A0.y, B0.y);
            v.z = fmaf(xv, A0.z, B0.z);
            v.w = fmaf(xv, A0.w, B0.w);
            *(float4*)(sxh + n * HFEAT + lane * 4) = v;
            float ss = v.x*a1.x + v.y*a1.y + v.z*a1.z + v.w*a1.w;
            float dd = v.x*a2.x + v.y*a2.y + v.z*a2.z + v.w*a2.w;
#pragma unroll
            for (int o = 4; o; o >>= 1) {
                ss += __shfl_xor_sync(0xffffffffu, ss, o);
                dd += __shfl_xor_sync(0xffffffffu, dd, o);
            }
            if ((lane & 7) == 0) {
                s_s[n * 4 + (lane >> 3)] = ss;
                s_d[n * 4 + (lane >> 3)] = dd;
            }
        }
    }
    __syncthreads();

    // ---- L0 fused softmax + aggregate + BN0 + relu (warp-per-node) ----
    {
        const int hh = lane >> 3;        // head (softmax group AND feature block)
        const int pi = lane & 7;
        float4 sc = *(const float4*)(sscale + lane * 4);
        float4 bs = *(const float4*)(sbias + lane * 4);
        for (int d = wid; d < NNODE; d += 16) {
            const int beg = sptr[d], end = sptr[d + 1];
            const float sd = s_d[d * 4 + hh];
            float mx = -1e30f;
            for (int p = beg + pi; p < end; p += 8) {
                float e = s_s[scsr[p] * 4 + hh] + sd;
                e = (e > 0.0f) ? e : 0.2f * e;
                sex[p * 4 + hh] = e;
                mx = fmaxf(mx, e);
            }
#pragma unroll
            for (int o = 4; o; o >>= 1)
                mx = fmaxf(mx, __shfl_xor_sync(0xffffffffu, mx, o));
            float sum = 0.0f;
            for (int p = beg + pi; p < end; p += 8) {
                float ex = __expf(sex[p * 4 + hh] - mx);
                sex[p * 4 + hh] = ex;
                sum += ex;
            }
#pragma unroll
            for (int o = 4; o; o >>= 1)
                sum += __shfl_xor_sync(0xffffffffu, sum, o);
            const float rv = 1.0f / sum;

            float4 acc = make_float4(0.f, 0.f, 0.f, 0.f);
            for (int p = beg; p < end; ++p) {
                float w = sex[p * 4 + hh];
                const float4 v = *(const float4*)(sxh + scsr[p] * HFEAT + lane * 4);
                acc.x = fmaf(w, v.x, acc.x);
                acc.y = fmaf(w, v.y, acc.y);
                acc.z = fmaf(w, v.z, acc.z);
                acc.w = fmaf(w, v.w, acc.w);
            }
            float4 r;
            r.x = fmaxf(fmaf(acc.x * rv, sc.x, bs.x), 0.0f);
            r.y = fmaxf(fmaf(acc.y * rv, sc.y, bs.y), 0.0f);
            r.z = fmaxf(fmaf(acc.z * rv, sc.z, bs.z), 0.0f);
            r.w = fmaxf(fmaf(acc.w * rv, sc.w, bs.w), 0.0f);
            *(float4*)(sh + d * HFEAT + lane * 4) = r;
        }
    }
    __syncthreads();

    // restage L1 attention + BN1 fold (ordered before use by gemm's barriers)
    if (tid < 128) {
        float sc = bn1g[tid] * rsqrtf(bn1v[tid] + 1e-5f);
        sscale[tid] = sc;
        sbias[tid]  = fmaf(g1b[tid] - bn1m[tid], sc, bn1b[tid]);
        satt[tid]       = g1as[tid];
        satt[128 + tid] = g1ad[tid];
    }

    // ==================== GAT layer 1 GEMM ====================
    gemm_sk(sh, sW, sxh, tid);
    __syncthreads();

    // ---- L1 scores: warp per node, full 32-lane reduce ----
    {
        float4 a1 = *(const float4*)(satt + lane * 4);
        float4 a2 = *(const float4*)(satt + 128 + lane * 4);
        for (int nd = wid; nd < NNODE; nd += 16) {
            float4 v = *(const float4*)(sxh + nd * HFEAT + lane * 4);
            float ss = v.x*a1.x + v.y*a1.y + v.z*a1.z + v.w*a1.w;
            float dd = v.x*a2.x + v.y*a2.y + v.z*a2.z + v.w*a2.w;
#pragma unroll
            for (int o = 16; o; o >>= 1) {
                ss += __shfl_xor_sync(0xffffffffu, ss, o);
                dd += __shfl_xor_sync(0xffffffffu, dd, o);
            }
            if (lane == 0) { s_s[nd] = ss; s_d[nd] = dd; }
        }
    }
    __syncthreads();

    // ---- L1 fused softmax + aggregate + BN1 + relu + POOL (warp-per-node) ----
    // Output rows never touch smem: each warp keeps a pool partial in regs,
    // then writes it into the (now dead) sh region.
    {
        float4 sc = *(const float4*)(sscale + lane * 4);
        float4 bs = *(const float4*)(sbias + lane * 4);
        float4 pacc = make_float4(0.f, 0.f, 0.f, 0.f);
        for (int d = wid; d < NNODE; d += 16) {
            const int beg = sptr[d], end = sptr[d + 1];
            const float sd = s_d[d];
            float mx = -1e30f;
            for (int p = beg + lane; p < end; p += 32) {
                float e = s_s[scsr[p]] + sd;
                e = (e > 0.0f) ? e : 0.2f * e;
                sex[p] = e;
                mx = fmaxf(mx, e);
            }
#pragma unroll
            for (int o = 16; o; o >>= 1)
                mx = fmaxf(mx, __shfl_xor_sync(0xffffffffu, mx, o));
            float sum = 0.0f;
            for (int p = beg + lane; p < end; p += 32) {
                float ex = __expf(sex[p] - mx);
                sex[p] = ex;
                sum += ex;
            }
#pragma unroll
            for (int o = 16; o; o >>= 1)
                sum += __shfl_xor_sync(0xffffffffu, sum, o);
            const float rv = 1.0f / sum;

            float4 acc = make_float4(0.f, 0.f, 0.f, 0.f);
            for (int p = beg; p < end; ++p) {
                float w = sex[p];
                const float4 v = *(const float4*)(sxh + scsr[p] * HFEAT + lane * 4);
                acc.x = fmaf(w, v.x, acc.x);
                acc.y = fmaf(w, v.y, acc.y);
                acc.z = fmaf(w, v.z, acc.z);
                acc.w = fmaf(w, v.w, acc.w);
            }
            pacc.x += fmaxf(fmaf(acc.x * rv, sc.x, bs.x), 0.0f);
            pacc.y += fmaxf(fmaf(acc.y * rv, sc.y, bs.y), 0.0f);
            pacc.z += fmaxf(fmaf(acc.z * rv, sc.z, bs.z), 0.0f);
            pacc.w += fmaxf(fmaf(acc.w * rv, sc.w, bs.w), 0.0f);
        }
        *(float4*)(sh + wid * HFEAT + lane * 4) = pacc;   // per-warp pool partial
    }
    __syncthreads();

    // ---- pool reduce: 16 warp-partials -> hp ----
    if (tid < 128) {
        float acc = 0.0f;
#pragma unroll
        for (int w = 0; w < 16; ++w) acc += sh[w * HFEAT + tid];
        hp[tid] = acc * (1.0f / 128.0f);
    }
    __syncthreads();

    // ---- MLP ----
    if (tid < 64) {
        float acc = b1[tid];
#pragma unroll 8
        for (int f = 0; f < 128; ++f) acc = fmaf(hp[f], w1[f * 64 + tid], acc);
        zz[tid] = fmaxf(acc, 0.0f);
    }
    __syncthreads();
    if (tid == 0) {
        float acc = b2[0];
#pragma unroll
        for (int j = 0; j < 64; ++j) acc = fmaf(zz[j], w2[j], acc);
        out[b] = acc;
    }
}

// ---------------------------------------------------------------------------
extern "C" void kernel_launch(void* const* d_in, const int* in_sizes, int n_in,
                              void* d_out, int out_size) {
    (void)in_sizes; (void)n_in; (void)out_size;
    const float* x    = (const float*)d_in[0];
    const int*   ei   = (const int*)d_in[1];
    const float* w_in = (const float*)d_in[2];
    const float* b_in = (const float*)d_in[3];
    const float* g0w  = (const float*)d_in[4];
    const float* g0as = (const float*)d_in[5];
    const float* g0ad = (const float*)d_in[6];
    const float* g0b  = (const float*)d_in[7];
    const float* bn0g = (const float*)d_in[8];
    const float* bn0b = (const float*)d_in[9];
    const float* bn0m = (const float*)d_in[10];
    const float* bn0v = (const float*)d_in[11];
    const float* g1w  = (const float*)d_in[12];
    const float* g1as = (const float*)d_in[13];
    const float* g1ad = (const float*)d_in[14];
    const float* g1b  = (const float*)d_in[15];
    const float* bn1g = (const float*)d_in[16];
    const float* bn1b = (const float*)d_in[17];
    const float* bn1m = (const float*)d_in[18];
    const float* bn1v = (const float*)d_in[19];
    const float* w1   = (const float*)d_in[20];
    const float* b1   = (const float*)d_in[21];
    const float* w2   = (const float*)d_in[22];
    const float* b2   = (const float*)d_in[23];
    float* out = (float*)d_out;

    cudaFuncSetAttribute(gnn_kernel,
                         cudaFuncAttributeMaxDynamicSharedMemorySize, SMEM_BYTES);

    setup_kernel<<<2, 1024>>>(ei, w_in, b_in, g0w);
    gnn_kernel<<<NGRAPH, NTHREADS, SMEM_BYTES>>>(
        x, g0as, g0ad, g0b, bn0g, bn0b, bn0m, bn0v,
        g1w, g1as, g1ad, g1b, bn1g, bn1b, bn1m, bn1v,
        w1, b1, w2, b2, out);
}

// round 11
// speedup vs baseline: 1.0397x; 1.0397x over previous
#include <cuda_runtime.h>

#define NNODE  128
#define NEDGE  1024
#define ETOT   1152
#define HFEAT  128
#define NGRAPH 1024
#define NTHREADS 512

// ---------------------------------------------------------------------------
// Device-global setup state (rebuilt every launch; deterministic).
// ---------------------------------------------------------------------------
__device__ int   g_csr_ptr[NNODE + 1];
__device__ int   g_csr_src[ETOT];
__device__ float g_t[HFEAT];                 // sorted relu breakpoints
__device__ float g_A[(HFEAT + 1) * HFEAT];   // interval slopes   (129 x 128)
__device__ float g_B[(HFEAT + 1) * HFEAT];   // interval offsets  (129 x 128)

// ---------------------------------------------------------------------------
// Combined setup: block 0 = CSR (warp-match stable ranks), block 1 = PWL.
// ---------------------------------------------------------------------------
__global__ void setup_kernel(const int* __restrict__ ei,
                             const float* __restrict__ w_in,
                             const float* __restrict__ b_in,
                             const float* __restrict__ W) {
    if (blockIdx.x == 0) {
        __shared__ int s_src[NEDGE];
        __shared__ int s_dst[NEDGE];
        __shared__ int hist[32][NNODE];
        __shared__ int cnt[NNODE];
        __shared__ int base[NNODE + 1];
        const int t = threadIdx.x;
        const int w = t >> 5, l = t & 31;
        s_src[t] = ei[t];
        s_dst[t] = ei[NEDGE + t];
        for (int i = t; i < 32 * NNODE; i += 1024) ((int*)hist)[i] = 0;
        __syncthreads();
        const int d = s_dst[t];
        unsigned mask = __match_any_sync(0xffffffffu, d);
        int lane_rank = __popc(mask & ((1u << l) - 1u));
        if (l == (__ffs(mask) - 1)) hist[w][d] = __popc(mask);
        __syncthreads();
        if (t < NNODE) {
            int acc = 0;
#pragma unroll
            for (int c = 0; c < 32; ++c) {
                int v = hist[c][t];
                hist[c][t] = acc;
                acc += v;
            }
            cnt[t] = acc;
        }
        __syncthreads();
        if (t == 0) {
            int acc = 0;
            for (int dd = 0; dd < NNODE; ++dd) { base[dd] = acc; acc += cnt[dd] + 1; }
            base[NNODE] = acc;
        }
        __syncthreads();
        if (t <= NNODE) g_csr_ptr[t] = base[t];
        g_csr_src[base[d] + hist[w][d] + lane_rank] = s_src[t];
        if (t < NNODE) g_csr_src[base[t] + cnt[t]] = t;   // self loop last
    } else {
        __shared__ float sw[HFEAT], sb[HFEAT], st[HFEAT];
        __shared__ int   ord[HFEAT];
        const int t = threadIdx.x;
        if (t >= HFEAT) return;
        sw[t] = w_in[t];
        sb[t] = b_in[t];
        __syncthreads();
        const float wf = sw[t], bf = sb[t];
        const float INF = __int_as_float(0x7f800000);
        float tf = (wf == 0.0f) ? INF : (-bf / wf);
        st[t] = tf;
        __syncthreads();
        tf = st[t];
        int rank = 0;
        for (int g = 0; g < HFEAT; ++g) {
            float tg = st[g];
            rank += (tg < tf) || (tg == tf && g < t);
        }
        ord[rank] = t;
        __syncthreads();
        g_t[t] = st[ord[t]];

        const int c = t;
        float A = 0.0f, B = 0.0f;
        for (int f = 0; f < HFEAT; ++f) {
            float Wfc = W[f * HFEAT + c];
            float w = sw[f];
            if (w < 0.0f)                       { A += w * Wfc; B += sb[f] * Wfc; }
            else if (w == 0.0f && sb[f] > 0.0f) { B += sb[f] * Wfc; }
        }
        g_A[c] = A; g_B[c] = B;
        for (int j = 0; j < HFEAT; ++j) {
            int f = ord[j];
            float w = sw[f];
            float Wfc = W[f * HFEAT + c];
            if (w > 0.0f)      { A += w * Wfc; B += sb[f] * Wfc; }
            else if (w < 0.0f) { A -= w * Wfc; B -= sb[f] * Wfc; }
            g_A[(j + 1) * HFEAT + c] = A;
            g_B[(j + 1) * HFEAT + c] = B;
        }
    }
}

// ---------------------------------------------------------------------------
// Shared memory layout (pitch 128). sW = g1w, filled by cp.async.bulk.
// ---------------------------------------------------------------------------
constexpr int OFF_SH    = 0;
constexpr int OFF_SXH   = OFF_SH  + NNODE * HFEAT;       // 16384
constexpr int OFF_SW    = OFF_SXH + NNODE * HFEAT;       // 16384
constexpr int OFF_SEX   = OFF_SW  + HFEAT * HFEAT;       // 4608
constexpr int OFF_SS    = OFF_SEX + ETOT * 4;            // 512
constexpr int OFF_SD    = OFF_SS  + 512;                 // 512
constexpr int OFF_SATT  = OFF_SD  + 512;                 // 256
constexpr int OFF_SCALE = OFF_SATT + 256;                // 128
constexpr int OFF_BIAS  = OFF_SCALE + 128;               // 128
constexpr int OFF_HP    = OFF_BIAS + 128;                // 128
constexpr int OFF_ZZ    = OFF_HP + 128;                  // 64
constexpr int OFF_XV    = OFF_ZZ + 64;                   // 128
constexpr int OFF_JX    = OFF_XV + 128;                  // 128
constexpr int OFF_MBAR  = OFF_JX + 128;                  // 4 (16B aligned)
constexpr int SM_FLOATS = OFF_MBAR + 4;
constexpr int SM_INTS   = 132 + ETOT;
constexpr int SMEM_BYTES = SM_FLOATS * 4 + SM_INTS * 4;   // ~222.8 KB

// ---------------------------------------------------------------------------
// Packed fp32x2 helpers (f32x2 ops are PTX-only)
// ---------------------------------------------------------------------------
__device__ __forceinline__ unsigned long long pack2(float a) {
    unsigned long long r;
    unsigned int ai = __float_as_uint(a);
    asm("mov.b64 %0, {%1, %1};" : "=l"(r) : "r"(ai));
    return r;
}
__device__ __forceinline__ void ffma2(unsigned long long& d,
                                      unsigned long long a,
                                      unsigned long long b) {
    asm("fma.rn.f32x2 %0, %1, %2, %0;" : "+l"(d) : "l"(a), "l"(b));
}
__device__ __forceinline__ void fadd2(unsigned long long& d,
                                      unsigned long long a) {
    asm("add.rn.f32x2 %0, %0, %1;" : "+l"(d) : "l"(a));
}

// ---------------------------------------------------------------------------
// Split-K GEMM: C = A @ W, all SMEM, 16 warps, 8x8 thread tiles.
// One internal __syncthreads(); all 512 threads must call.
// ---------------------------------------------------------------------------
__device__ __forceinline__ void gemm_sk(const float* __restrict__ A,
                                        const float* __restrict__ sW,
                                        float* __restrict__ C, int tid) {
    const int w  = tid >> 5;
    const int l  = tid & 31;
    const int kh = w >> 3;
    const int r0 = (w & 7) * 16 + (l >> 4) * 8;
    const int ca = (l & 15) * 4;
    const int k0 = kh * 64;

    unsigned long long acc[8][4];
#pragma unroll
    for (int i = 0; i < 8; ++i)
#pragma unroll
        for (int j = 0; j < 4; ++j) acc[i][j] = 0ull;

#pragma unroll 2
    for (int k = k0; k < k0 + 64; k += 2) {
        float2 a[8];
#pragma unroll
        for (int i = 0; i < 8; ++i)
            a[i] = *(const float2*)(A + (r0 + i) * HFEAT + k);
        ulonglong2 w00 = *(const ulonglong2*)(sW + k * HFEAT + ca);
        ulonglong2 w01 = *(const ulonglong2*)(sW + k * HFEAT + ca + 64);
        ulonglong2 w10 = *(const ulonglong2*)(sW + (k + 1) * HFEAT + ca);
        ulonglong2 w11 = *(const ulonglong2*)(sW + (k + 1) * HFEAT + ca + 64);
#pragma unroll
        for (int i = 0; i < 8; ++i) {
            unsigned long long ax = pack2(a[i].x);
            unsigned long long ay = pack2(a[i].y);
            ffma2(acc[i][0], ax, w00.x);
            ffma2(acc[i][1], ax, w00.y);
            ffma2(acc[i][2], ax, w01.x);
            ffma2(acc[i][3], ax, w01.y);
            ffma2(acc[i][0], ay, w10.x);
            ffma2(acc[i][1], ay, w10.y);
            ffma2(acc[i][2], ay, w11.x);
            ffma2(acc[i][3], ay, w11.y);
        }
    }

    if (kh == 1) {
#pragma unroll
        for (int i = 0; i < 8; ++i) {
            ulonglong2 s0, s1;
            s0.x = acc[i][0]; s0.y = acc[i][1];
            s1.x = acc[i][2]; s1.y = acc[i][3];
            *(ulonglong2*)(C + (r0 + i) * HFEAT + ca)      = s0;
            *(ulonglong2*)(C + (r0 + i) * HFEAT + ca + 64) = s1;
        }
    }
    __syncthreads();
    if (kh == 0) {
#pragma unroll
        for (int i = 0; i < 8; ++i) {
            ulonglong2 p0 = *(const ulonglong2*)(C + (r0 + i) * HFEAT + ca);
            ulonglong2 p1 = *(const ulonglong2*)(C + (r0 + i) * HFEAT + ca + 64);
            fadd2(acc[i][0], p0.x);
            fadd2(acc[i][1], p0.y);
            fadd2(acc[i][2], p1.x);
            fadd2(acc[i][3], p1.y);
            ulonglong2 s0, s1;
            s0.x = acc[i][0]; s0.y = acc[i][1];
            s1.x = acc[i][2]; s1.y = acc[i][3];
            *(ulonglong2*)(C + (r0 + i) * HFEAT + ca)      = s0;
            *(ulonglong2*)(C + (r0 + i) * HFEAT + ca + 64) = s1;
        }
    }
}

__global__ __launch_bounds__(NTHREADS, 1)
void gnn_kernel(const float* __restrict__ x,
                const float* __restrict__ g0as, const float* __restrict__ g0ad,
                const float* __restrict__ g0b,
                const float* __restrict__ bn0g, const float* __restrict__ bn0b,
                const float* __restrict__ bn0m, const float* __restrict__ bn0v,
                const float* __restrict__ g1w, const float* __restrict__ g1as,
                const float* __restrict__ g1ad, const float* __restrict__ g1b,
                const float* __restrict__ bn1g, const float* __restrict__ bn1b,
                const float* __restrict__ bn1m, const float* __restrict__ bn1v,
                const float* __restrict__ w1, const float* __restrict__ b1,
                const float* __restrict__ w2, const float* __restrict__ b2,
                float* __restrict__ out) {
    extern __shared__ float smem[];
    float* sh    = smem + OFF_SH;     // L0 output; later: pool partials
    float* sxh   = smem + OFF_SXH;
    float* sW    = smem + OFF_SW;
    float* sex   = smem + OFF_SEX;
    float* s_s   = smem + OFF_SS;
    float* s_d   = smem + OFF_SD;
    float* satt  = smem + OFF_SATT;
    float* sscale= smem + OFF_SCALE;
    float* sbias = smem + OFF_BIAS;
    float* hp    = smem + OFF_HP;
    float* zz    = smem + OFF_ZZ;
    float* sxv   = smem + OFF_XV;
    int*   jidx  = (int*)(smem + OFF_JX);
    int*   sptr  = (int*)(smem + SM_FLOATS);
    int*   scsr  = sptr + 132;        // stores src*128 (row offset in floats)

    const int tid  = threadIdx.x;
    const int wid  = tid >> 5;
    const int lane = tid & 31;
    const int b    = blockIdx.x;
    const unsigned mbar = (unsigned)__cvta_generic_to_shared(smem + OFF_MBAR);

    // ---- init ----
    for (int i = tid; i <= NNODE; i += NTHREADS) sptr[i] = g_csr_ptr[i];
    for (int i = tid; i < ETOT; i += NTHREADS)   scsr[i] = g_csr_src[i] << 7;
    if (tid == 0)
        asm volatile("mbarrier.init.shared.b64 [%0], %1;" :: "r"(mbar), "r"(1) : "memory");
    if (tid < 128) {
        satt[tid]       = g0as[tid];
        satt[128 + tid] = g0ad[tid];
        float sc = bn0g[tid] * rsqrtf(bn0v[tid] + 1e-5f);
        sscale[tid] = sc;
        sbias[tid]  = fmaf(g0b[tid] - bn0m[tid], sc, bn0b[tid]);
        float xv = x[b * NNODE + tid];
        sxv[tid] = xv;
        int lo = 0, hi = HFEAT;
        while (lo < hi) {
            int mid = (lo + hi) >> 1;
            if (g_t[mid] <= xv) lo = mid + 1; else hi = mid;
        }
        jidx[tid] = lo;
    }
    __syncthreads();

    // async W1 load: completes while PWL + L0 phases run
    if (tid == 0) {
        unsigned sw_addr = (unsigned)__cvta_generic_to_shared(sW);
        asm volatile("mbarrier.arrive.expect_tx.shared.b64 _, [%0], %1;"
                     :: "r"(mbar), "r"(HFEAT * HFEAT * 4) : "memory");
        asm volatile("cp.async.bulk.shared::cta.global.mbarrier::complete_tx::bytes "
                     "[%0], [%1], %2, [%3];"
                     :: "r"(sw_addr), "l"(g1w), "r"(HFEAT * HFEAT * 4), "r"(mbar)
                     : "memory");
    }

    // ---- xh0 = x*A_j + B_j (PWL) with fused L0 scores, software-pipelined ----
    {
        float4 a1 = *(const float4*)(satt + lane * 4);
        float4 a2 = *(const float4*)(satt + 128 + lane * 4);
        const int l4 = lane * 4;
        int n = wid;
        int   j0  = jidx[n];
        float xv0 = sxv[n];
        float4 A0 = *(const float4*)(g_A + j0 * HFEAT + l4);
        float4 B0 = *(const float4*)(g_B + j0 * HFEAT + l4);
        for (; n < NNODE; n += 16) {
            float xv = xv0;
            float4 Ac = A0, Bc = B0;
            int n2 = n + 16;
            if (n2 < NNODE) {        // prefetch next node's tables
                int j2 = jidx[n2];
                xv0 = sxv[n2];
                A0 = *(const float4*)(g_A + j2 * HFEAT + l4);
                B0 = *(const float4*)(g_B + j2 * HFEAT + l4);
            }
            float4 v;
            v.x = fmaf(xv, Ac.x, Bc.x);
            v.y = fmaf(xv, Ac.y, Bc.y);
            v.z = fmaf(xv, Ac.z, Bc.z);
            v.w = fmaf(xv, Ac.w, Bc.w);
            *(float4*)(sxh + n * HFEAT + l4) = v;
            float ss = v.x*a1.x + v.y*a1.y + v.z*a1.z + v.w*a1.w;
            float dd = v.x*a2.x + v.y*a2.y + v.z*a2.z + v.w*a2.w;
#pragma unroll
            for (int o = 4; o; o >>= 1) {
                ss += __shfl_xor_sync(0xffffffffu, ss, o);
                dd += __shfl_xor_sync(0xffffffffu, dd, o);
            }
            if ((lane & 7) == 0) {
                s_s[n * 4 + (lane >> 3)] = ss;
                s_d[n * 4 + (lane >> 3)] = dd;
            }
        }
    }
    __syncthreads();

    // ---- L0 fused softmax + aggregate + BN0 + relu (warp-per-node) ----
    {
        const int hh = lane >> 3;
        const int pi = lane & 7;
        const int l4 = lane * 4;
        float4 sc = *(const float4*)(sscale + l4);
        float4 bs = *(const float4*)(sbias + l4);
        for (int d = wid; d < NNODE; d += 16) {
            const int beg = sptr[d], end = sptr[d + 1];
            const float sd = s_d[d * 4 + hh];
            float mx = -1e30f;
            for (int p = beg + pi; p < end; p += 8) {
                float e = s_s[(scsr[p] >> 5) + hh] + sd;
                e = (e > 0.0f) ? e : 0.2f * e;
                sex[(p << 2) + hh] = e;
                mx = fmaxf(mx, e);
            }
#pragma unroll
            for (int o = 4; o; o >>= 1)
                mx = fmaxf(mx, __shfl_xor_sync(0xffffffffu, mx, o));
            float sum = 0.0f;
            for (int p = beg + pi; p < end; p += 8) {
                float ex = __expf(sex[(p << 2) + hh] - mx);
                sex[(p << 2) + hh] = ex;
                sum += ex;
            }
#pragma unroll
            for (int o = 4; o; o >>= 1)
                sum += __shfl_xor_sync(0xffffffffu, sum, o);
            const float rv = 1.0f / sum;

            // pipelined aggregate (>=1 edge guaranteed: self loop)
            float4 acc = make_float4(0.f, 0.f, 0.f, 0.f);
            int p = beg;
            float wv = sex[(p << 2) + hh];
            float4 v = *(const float4*)(sxh + scsr[p] + l4);
            for (++p; p < end; ++p) {
                float wn = sex[(p << 2) + hh];
                float4 vn = *(const float4*)(sxh + scsr[p] + l4);
                acc.x = fmaf(wv, v.x, acc.x);
                acc.y = fmaf(wv, v.y, acc.y);
                acc.z = fmaf(wv, v.z, acc.z);
                acc.w = fmaf(wv, v.w, acc.w);
                wv = wn; v = vn;
            }
            acc.x = fmaf(wv, v.x, acc.x);
            acc.y = fmaf(wv, v.y, acc.y);
            acc.z = fmaf(wv, v.z, acc.z);
            acc.w = fmaf(wv, v.w, acc.w);

            float4 r;
            r.x = fmaxf(fmaf(acc.x * rv, sc.x, bs.x), 0.0f);
            r.y = fmaxf(fmaf(acc.y * rv, sc.y, bs.y), 0.0f);
            r.z = fmaxf(fmaf(acc.z * rv, sc.z, bs.z), 0.0f);
            r.w = fmaxf(fmaf(acc.w * rv, sc.w, bs.w), 0.0f);
            *(float4*)(sh + d * HFEAT + l4) = r;
        }
    }
    __syncthreads();

    // restage L1 attention + BN1 fold
    if (tid < 128) {
        float sc = bn1g[tid] * rsqrtf(bn1v[tid] + 1e-5f);
        sscale[tid] = sc;
        sbias[tid]  = fmaf(g1b[tid] - bn1m[tid], sc, bn1b[tid]);
        satt[tid]       = g1as[tid];
        satt[128 + tid] = g1ad[tid];
    }

    // wait for W1 bulk copy (long since complete)
    asm volatile(
        "{\n\t"
        ".reg .pred P1;\n\t"
        "W_%=:\n\t"
        "mbarrier.try_wait.parity.acquire.cta.shared::cta.b64 P1, [%0], 0, 0x989680;\n\t"
        "@P1 bra D_%=;\n\t"
        "bra W_%=;\n\t"
        "D_%=:\n\t"
        "}" :: "r"(mbar) : "memory");

    // ==================== GAT layer 1 GEMM ====================
    gemm_sk(sh, sW, sxh, tid);
    __syncthreads();

    // ---- L1 scores: warp per node, full 32-lane reduce ----
    {
        float4 a1 = *(const float4*)(satt + lane * 4);
        float4 a2 = *(const float4*)(satt + 128 + lane * 4);
        for (int nd = wid; nd < NNODE; nd += 16) {
            float4 v = *(const float4*)(sxh + nd * HFEAT + lane * 4);
            float ss = v.x*a1.x + v.y*a1.y + v.z*a1.z + v.w*a1.w;
            float dd = v.x*a2.x + v.y*a2.y + v.z*a2.z + v.w*a2.w;
#pragma unroll
            for (int o = 16; o; o >>= 1) {
                ss += __shfl_xor_sync(0xffffffffu, ss, o);
                dd += __shfl_xor_sync(0xffffffffu, dd, o);
            }
            if (lane == 0) { s_s[nd] = ss; s_d[nd] = dd; }
        }
    }
    __syncthreads();

    // ---- L1 fused softmax + aggregate + BN1 + relu + POOL (warp-per-node) ----
    {
        const int l4 = lane * 4;
        float4 sc = *(const float4*)(sscale + l4);
        float4 bs = *(const float4*)(sbias + l4);
        float4 pacc = make_float4(0.f, 0.f, 0.f, 0.f);
        for (int d = wid; d < NNODE; d += 16) {
            const int beg = sptr[d], end = sptr[d + 1];
            const float sd = s_d[d];
            float mx = -1e30f;
            for (int p = beg + lane; p < end; p += 32) {
                float e = s_s[scsr[p] >> 7] + sd;
                e = (e > 0.0f) ? e : 0.2f * e;
                sex[p] = e;
                mx = fmaxf(mx, e);
            }
#pragma unroll
            for (int o = 16; o; o >>= 1)
                mx = fmaxf(mx, __shfl_xor_sync(0xffffffffu, mx, o));
            float sum = 0.0f;
            for (int p = beg + lane; p < end; p += 32) {
                float ex = __expf(sex[p] - mx);
                sex[p] = ex;
                sum += ex;
            }
#pragma unroll
            for (int o = 16; o; o >>= 1)
                sum += __shfl_xor_sync(0xffffffffu, sum, o);
            const float rv = 1.0f / sum;

            float4 acc = make_float4(0.f, 0.f, 0.f, 0.f);
            int p = beg;
            float wv = sex[p];
            float4 v = *(const float4*)(sxh + scsr[p] + l4);
            for (++p; p < end; ++p) {
                float wn = sex[p];
                float4 vn = *(const float4*)(sxh + scsr[p] + l4);
                acc.x = fmaf(wv, v.x, acc.x);
                acc.y = fmaf(wv, v.y, acc.y);
                acc.z = fmaf(wv, v.z, acc.z);
                acc.w = fmaf(wv, v.w, acc.w);
                wv = wn; v = vn;
            }
            acc.x = fmaf(wv, v.x, acc.x);
            acc.y = fmaf(wv, v.y, acc.y);
            acc.z = fmaf(wv, v.z, acc.z);
            acc.w = fmaf(wv, v.w, acc.w);

            pacc.x += fmaxf(fmaf(acc.x * rv, sc.x, bs.x), 0.0f);
            pacc.y += fmaxf(fmaf(acc.y * rv, sc.y, bs.y), 0.0f);
            pacc.z += fmaxf(fmaf(acc.z * rv, sc.z, bs.z), 0.0f);
            pacc.w += fmaxf(fmaf(acc.w * rv, sc.w, bs.w), 0.0f);
        }
        *(float4*)(sh + wid * HFEAT + l4) = pacc;   // per-warp pool partial
    }
    __syncthreads();

    // ---- pool reduce ----
    if (tid < 128) {
        float acc = 0.0f;
#pragma unroll
        for (int w = 0; w < 16; ++w) acc += sh[w * HFEAT + tid];
        hp[tid] = acc * (1.0f / 128.0f);
    }
    __syncthreads();

    // ---- MLP ----
    if (tid < 64) {
        float acc = b1[tid];
#pragma unroll 8
        for (int f = 0; f < 128; ++f) acc = fmaf(hp[f], w1[f * 64 + tid], acc);
        zz[tid] = fmaxf(acc, 0.0f);
    }
    __syncthreads();
    if (tid == 0) {
        float acc = b2[0];
#pragma unroll
        for (int j = 0; j < 64; ++j) acc = fmaf(zz[j], w2[j], acc);
        out[b] = acc;
    }
}

// ---------------------------------------------------------------------------
extern "C" void kernel_launch(void* const* d_in, const int* in_sizes, int n_in,
                              void* d_out, int out_size) {
    (void)in_sizes; (void)n_in; (void)out_size;
    const float* x    = (const float*)d_in[0];
    const int*   ei   = (const int*)d_in[1];
    const float* w_in = (const float*)d_in[2];
    const float* b_in = (const float*)d_in[3];
    const float* g0w  = (const float*)d_in[4];
    const float* g0as = (const float*)d_in[5];
    const float* g0ad = (const float*)d_in[6];
    const float* g0b  = (const float*)d_in[7];
    const float* bn0g = (const float*)d_in[8];
    const float* bn0b = (const float*)d_in[9];
    const float* bn0m = (const float*)d_in[10];
    const float* bn0v = (const float*)d_in[11];
    const float* g1w  = (const float*)d_in[12];
    const float* g1as = (const float*)d_in[13];
    const float* g1ad = (const float*)d_in[14];
    const float* g1b  = (const float*)d_in[15];
    const float* bn1g = (const float*)d_in[16];
    const float* bn1b = (const float*)d_in[17];
    const float* bn1m = (const float*)d_in[18];
    const float* bn1v = (const float*)d_in[19];
    const float* w1   = (const float*)d_in[20];
    const float* b1   = (const float*)d_in[21];
    const float* w2   = (const float*)d_in[22];
    const float* b2   = (const float*)d_in[23];
    float* out = (float*)d_out;

    cudaFuncSetAttribute(gnn_kernel,
                         cudaFuncAttributeMaxDynamicSharedMemorySize, SMEM_BYTES);

    setup_kernel<<<2, 1024>>>(ei, w_in, b_in, g0w);
    gnn_kernel<<<NGRAPH, NTHREADS, SMEM_BYTES>>>(
        x, g0as, g0ad, g0b, bn0g, bn0b, bn0m, bn0v,
        g1w, g1as, g1ad, g1b, bn1g, bn1b, bn1m, bn1v,
        w1, b1, w2, b2, out);
}

// round 12
// speedup vs baseline: 1.1011x; 1.0590x over previous
#include <cuda_runtime.h>

#define NNODE  128
#define NEDGE  1024
#define ETOT   1152
#define HFEAT  128
#define NGRAPH 1024
#define NTHREADS 512

// ---------------------------------------------------------------------------
// Device-global setup state (rebuilt every launch; deterministic).
// 16B-aligned + padded so cp.async.bulk can copy them.
// ---------------------------------------------------------------------------
__device__ __align__(16) int   g_csr_ptr[132];            // 129 used, padded
__device__ __align__(16) int   g_csr_src[ETOT];
__device__ __align__(16) float g_t[HFEAT];                // sorted breakpoints
__device__ __align__(16) float g_A[(HFEAT + 1) * HFEAT];  // interval slopes
__device__ __align__(16) float g_B[(HFEAT + 1) * HFEAT];  // interval offsets

// ---------------------------------------------------------------------------
// Combined setup: block 0 = CSR (warp-match stable ranks), block 1 = PWL.
// ---------------------------------------------------------------------------
__global__ void setup_kernel(const int* __restrict__ ei,
                             const float* __restrict__ w_in,
                             const float* __restrict__ b_in,
                             const float* __restrict__ W) {
    if (blockIdx.x == 0) {
        __shared__ int s_src[NEDGE];
        __shared__ int s_dst[NEDGE];
        __shared__ int hist[32][NNODE];
        __shared__ int cnt[NNODE];
        __shared__ int base[NNODE + 1];
        const int t = threadIdx.x;
        const int w = t >> 5, l = t & 31;
        s_src[t] = ei[t];
        s_dst[t] = ei[NEDGE + t];
        for (int i = t; i < 32 * NNODE; i += 1024) ((int*)hist)[i] = 0;
        __syncthreads();
        const int d = s_dst[t];
        unsigned mask = __match_any_sync(0xffffffffu, d);
        int lane_rank = __popc(mask & ((1u << l) - 1u));
        if (l == (__ffs(mask) - 1)) hist[w][d] = __popc(mask);
        __syncthreads();
        if (t < NNODE) {
            int acc = 0;
#pragma unroll
            for (int c = 0; c < 32; ++c) {
                int v = hist[c][t];
                hist[c][t] = acc;
                acc += v;
            }
            cnt[t] = acc;
        }
        __syncthreads();
        if (t == 0) {
            int acc = 0;
            for (int dd = 0; dd < NNODE; ++dd) { base[dd] = acc; acc += cnt[dd] + 1; }
            base[NNODE] = acc;
        }
        __syncthreads();
        if (t <= NNODE) g_csr_ptr[t] = base[t];
        g_csr_src[base[d] + hist[w][d] + lane_rank] = s_src[t];
        if (t < NNODE) g_csr_src[base[t] + cnt[t]] = t;   // self loop last
    } else {
        __shared__ float sw[HFEAT], sb[HFEAT], st[HFEAT];
        __shared__ int   ord[HFEAT];
        const int t = threadIdx.x;
        if (t >= HFEAT) return;
        sw[t] = w_in[t];
        sb[t] = b_in[t];
        __syncthreads();
        const float wf = sw[t], bf = sb[t];
        const float INF = __int_as_float(0x7f800000);
        float tf = (wf == 0.0f) ? INF : (-bf / wf);
        st[t] = tf;
        __syncthreads();
        tf = st[t];
        int rank = 0;
        for (int g = 0; g < HFEAT; ++g) {
            float tg = st[g];
            rank += (tg < tf) || (tg == tf && g < t);
        }
        ord[rank] = t;
        __syncthreads();
        g_t[t] = st[ord[t]];

        const int c = t;
        float A = 0.0f, B = 0.0f;
        for (int f = 0; f < HFEAT; ++f) {
            float Wfc = W[f * HFEAT + c];
            float w = sw[f];
            if (w < 0.0f)                       { A += w * Wfc; B += sb[f] * Wfc; }
            else if (w == 0.0f && sb[f] > 0.0f) { B += sb[f] * Wfc; }
        }
        g_A[c] = A; g_B[c] = B;
        for (int j = 0; j < HFEAT; ++j) {
            int f = ord[j];
            float w = sw[f];
            float Wfc = W[f * HFEAT + c];
            if (w > 0.0f)      { A += w * Wfc; B += sb[f] * Wfc; }
            else if (w < 0.0f) { A -= w * Wfc; B -= sb[f] * Wfc; }
            g_A[(j + 1) * HFEAT + c] = A;
            g_B[(j + 1) * HFEAT + c] = B;
        }
    }
}

// ---------------------------------------------------------------------------
// Shared memory layout (floats). sW/sptr/scsr filled by cp.async.bulk.
// ---------------------------------------------------------------------------
constexpr int OFF_SH    = 0;
constexpr int OFF_SXH   = OFF_SH  + NNODE * HFEAT;       // 16384
constexpr int OFF_SW    = OFF_SXH + NNODE * HFEAT;       // 16384
constexpr int OFF_SEX   = OFF_SW  + HFEAT * HFEAT;       // 4608
constexpr int OFF_SS    = OFF_SEX + ETOT * 4;            // 512
constexpr int OFF_SD    = OFF_SS  + 512;                 // 512
constexpr int OFF_SATT  = OFF_SD  + 512;                 // 256
constexpr int OFF_SCALE = OFF_SATT + 256;                // 128
constexpr int OFF_BIAS  = OFF_SCALE + 128;               // 128
constexpr int OFF_HP    = OFF_BIAS + 128;                // 128
constexpr int OFF_ZZ    = OFF_HP + 128;                  // 64
constexpr int OFF_XV    = OFF_ZZ + 64;                   // 128
constexpr int OFF_ST    = OFF_XV + 128;                  // 128 (staged g_t)
constexpr int OFF_MBAR  = OFF_ST + 128;                  // 4
constexpr int SM_FLOATS = OFF_MBAR + 4;                  // 55748 (x4 = 16-mult)
constexpr int SM_INTS   = 132 + ETOT;
constexpr int SMEM_BYTES = SM_FLOATS * 4 + SM_INTS * 4;  // 228128 B

constexpr int TX_BYTES = 132 * 4 + ETOT * 4 + HFEAT * HFEAT * 4;  // 70672

// ---------------------------------------------------------------------------
// Packed fp32x2 helpers (f32x2 ops are PTX-only)
// ---------------------------------------------------------------------------
__device__ __forceinline__ unsigned long long pack2(float a) {
    unsigned long long r;
    unsigned int ai = __float_as_uint(a);
    asm("mov.b64 %0, {%1, %1};" : "=l"(r) : "r"(ai));
    return r;
}
__device__ __forceinline__ void ffma2(unsigned long long& d,
                                      unsigned long long a,
                                      unsigned long long b) {
    asm("fma.rn.f32x2 %0, %1, %2, %0;" : "+l"(d) : "l"(a), "l"(b));
}
__device__ __forceinline__ void fadd2(unsigned long long& d,
                                      unsigned long long a) {
    asm("add.rn.f32x2 %0, %0, %1;" : "+l"(d) : "l"(a));
}

// ---------------------------------------------------------------------------
// Split-K GEMM: C = A @ W, all SMEM, 16 warps, 8x8 thread tiles.
// One internal __syncthreads(); all 512 threads must call.
// ---------------------------------------------------------------------------
__device__ __forceinline__ void gemm_sk(const float* __restrict__ A,
                                        const float* __restrict__ sW,
                                        float* __restrict__ C, int tid) {
    const int w  = tid >> 5;
    const int l  = tid & 31;
    const int kh = w >> 3;
    const int r0 = (w & 7) * 16 + (l >> 4) * 8;
    const int ca = (l & 15) * 4;
    const int k0 = kh * 64;

    unsigned long long acc[8][4];
#pragma unroll
    for (int i = 0; i < 8; ++i)
#pragma unroll
        for (int j = 0; j < 4; ++j) acc[i][j] = 0ull;

#pragma unroll 2
    for (int k = k0; k < k0 + 64; k += 2) {
        float2 a[8];
#pragma unroll
        for (int i = 0; i < 8; ++i)
            a[i] = *(const float2*)(A + (r0 + i) * HFEAT + k);
        ulonglong2 w00 = *(const ulonglong2*)(sW + k * HFEAT + ca);
        ulonglong2 w01 = *(const ulonglong2*)(sW + k * HFEAT + ca + 64);
        ulonglong2 w10 = *(const ulonglong2*)(sW + (k + 1) * HFEAT + ca);
        ulonglong2 w11 = *(const ulonglong2*)(sW + (k + 1) * HFEAT + ca + 64);
#pragma unroll
        for (int i = 0; i < 8; ++i) {
            unsigned long long ax = pack2(a[i].x);
            unsigned long long ay = pack2(a[i].y);
            ffma2(acc[i][0], ax, w00.x);
            ffma2(acc[i][1], ax, w00.y);
            ffma2(acc[i][2], ax, w01.x);
            ffma2(acc[i][3], ax, w01.y);
            ffma2(acc[i][0], ay, w10.x);
            ffma2(acc[i][1], ay, w10.y);
            ffma2(acc[i][2], ay, w11.x);
            ffma2(acc[i][3], ay, w11.y);
        }
    }

    if (kh == 1) {
#pragma unroll
        for (int i = 0; i < 8; ++i) {
            ulonglong2 s0, s1;
            s0.x = acc[i][0]; s0.y = acc[i][1];
            s1.x = acc[i][2]; s1.y = acc[i][3];
            *(ulonglong2*)(C + (r0 + i) * HFEAT + ca)      = s0;
            *(ulonglong2*)(C + (r0 + i) * HFEAT + ca + 64) = s1;
        }
    }
    __syncthreads();
    if (kh == 0) {
#pragma unroll
        for (int i = 0; i < 8; ++i) {
            ulonglong2 p0 = *(const ulonglong2*)(C + (r0 + i) * HFEAT + ca);
            ulonglong2 p1 = *(const ulonglong2*)(C + (r0 + i) * HFEAT + ca + 64);
            fadd2(acc[i][0], p0.x);
            fadd2(acc[i][1], p0.y);
            fadd2(acc[i][2], p1.x);
            fadd2(acc[i][3], p1.y);
            ulonglong2 s0, s1;
            s0.x = acc[i][0]; s0.y = acc[i][1];
            s1.x = acc[i][2]; s1.y = acc[i][3];
            *(ulonglong2*)(C + (r0 + i) * HFEAT + ca)      = s0;
            *(ulonglong2*)(C + (r0 + i) * HFEAT + ca + 64) = s1;
        }
    }
}

__global__ __launch_bounds__(NTHREADS, 1)
void gnn_kernel(const float* __restrict__ x,
                const float* __restrict__ g0as, const float* __restrict__ g0ad,
                const float* __restrict__ g0b,
                const float* __restrict__ bn0g, const float* __restrict__ bn0b,
                const float* __restrict__ bn0m, const float* __restrict__ bn0v,
                const float* __restrict__ g1w, const float* __restrict__ g1as,
                const float* __restrict__ g1ad, const float* __restrict__ g1b,
                const float* __restrict__ bn1g, const float* __restrict__ bn1b,
                const float* __restrict__ bn1m, const float* __restrict__ bn1v,
                const float* __restrict__ w1, const float* __restrict__ b1,
                const float* __restrict__ w2, const float* __restrict__ b2,
                float* __restrict__ out) {
    extern __shared__ float smem[];
    float* sh    = smem + OFF_SH;     // L0 output; later: pool partials
    float* sxh   = smem + OFF_SXH;
    float* sW    = smem + OFF_SW;
    float* sex   = smem + OFF_SEX;
    float* s_s   = smem + OFF_SS;
    float* s_d   = smem + OFF_SD;
    float* satt  = smem + OFF_SATT;
    float* sscale= smem + OFF_SCALE;
    float* sbias = smem + OFF_BIAS;
    float* hp    = smem + OFF_HP;
    float* zz    = smem + OFF_ZZ;
    float* sxv   = smem + OFF_XV;
    float* st    = smem + OFF_ST;
    int*   sptr  = (int*)(smem + SM_FLOATS);
    int*   scsr  = sptr + 132;        // raw src indices

    const int tid  = threadIdx.x;
    const int wid  = tid >> 5;
    const int lane = tid & 31;
    const int b    = blockIdx.x;
    const unsigned mbar = (unsigned)__cvta_generic_to_shared(smem + OFF_MBAR);

    // ---- init (no CSR staging here; it goes async) ----
    if (tid == 0)
        asm volatile("mbarrier.init.shared.b64 [%0], %1;" :: "r"(mbar), "r"(1) : "memory");
    if (tid < 128) {
        satt[tid]       = g0as[tid];
        satt[128 + tid] = g0ad[tid];
        float sc = bn0g[tid] * rsqrtf(bn0v[tid] + 1e-5f);
        sscale[tid] = sc;
        sbias[tid]  = fmaf(g0b[tid] - bn0m[tid], sc, bn0b[tid]);
        sxv[tid] = x[b * NNODE + tid];
        st[tid]  = g_t[tid];
    }
    __syncthreads();

    // async loads: CSR (ptr+src) + W1; all land before L0 softmax wait
    if (tid == 0) {
        unsigned a_sw   = (unsigned)__cvta_generic_to_shared(sW);
        unsigned a_sptr = (unsigned)__cvta_generic_to_shared(sptr);
        unsigned a_scsr = (unsigned)__cvta_generic_to_shared(scsr);
        asm volatile("mbarrier.arrive.expect_tx.shared.b64 _, [%0], %1;"
                     :: "r"(mbar), "r"(TX_BYTES) : "memory");
        asm volatile("cp.async.bulk.shared::cta.global.mbarrier::complete_tx::bytes "
                     "[%0], [%1], %2, [%3];"
                     :: "r"(a_sw), "l"(g1w), "r"(HFEAT * HFEAT * 4), "r"(mbar) : "memory");
        asm volatile("cp.async.bulk.shared::cta.global.mbarrier::complete_tx::bytes "
                     "[%0], [%1], %2, [%3];"
                     :: "r"(a_sptr), "l"(g_csr_ptr), "r"(132 * 4), "r"(mbar) : "memory");
        asm volatile("cp.async.bulk.shared::cta.global.mbarrier::complete_tx::bytes "
                     "[%0], [%1], %2, [%3];"
                     :: "r"(a_scsr), "l"(g_csr_src), "r"(ETOT * 4), "r"(mbar) : "memory");
    }

    // ---- xh0 = x*A_j + B_j (PWL) with fused L0 scores; j via ballot count ----
    {
        float4 a1 = *(const float4*)(satt + lane * 4);
        float4 a2 = *(const float4*)(satt + 128 + lane * 4);
        const int l4 = lane * 4;
        int n = wid;
        float xv0 = sxv[n];
        int j0 = 0;
#pragma unroll
        for (int q = 0; q < 4; ++q)
            j0 += __popc(__ballot_sync(0xffffffffu, st[lane + 32 * q] <= xv0));
        float4 A0 = *(const float4*)(g_A + j0 * HFEAT + l4);
        float4 B0 = *(const float4*)(g_B + j0 * HFEAT + l4);
        for (; n < NNODE; n += 16) {
            float xv = xv0;
            float4 Ac = A0, Bc = B0;
            int n2 = n + 16;
            if (n2 < NNODE) {        // prefetch next node's tables
                xv0 = sxv[n2];
                int j2 = 0;
#pragma unroll
                for (int q = 0; q < 4; ++q)
                    j2 += __popc(__ballot_sync(0xffffffffu, st[lane + 32 * q] <= xv0));
                A0 = *(const float4*)(g_A + j2 * HFEAT + l4);
                B0 = *(const float4*)(g_B + j2 * HFEAT + l4);
            }
            float4 v;
            v.x = fmaf(xv, Ac.x, Bc.x);
            v.y = fmaf(xv, Ac.y, Bc.y);
            v.z = fmaf(xv, Ac.z, Bc.z);
            v.w = fmaf(xv, Ac.w, Bc.w);
            *(float4*)(sxh + n * HFEAT + l4) = v;
            float ss = v.x*a1.x + v.y*a1.y + v.z*a1.z + v.w*a1.w;
            float dd = v.x*a2.x + v.y*a2.y + v.z*a2.z + v.w*a2.w;
#pragma unroll
            for (int o = 4; o; o >>= 1) {
                ss += __shfl_xor_sync(0xffffffffu, ss, o);
                dd += __shfl_xor_sync(0xffffffffu, dd, o);
            }
            if ((lane & 7) == 0) {
                s_s[n * 4 + (lane >> 3)] = ss;
                s_d[n * 4 + (lane >> 3)] = dd;
            }
        }
    }
    __syncthreads();

    // wait for async CSR + W1 (all threads)
    asm volatile(
        "{\n\t"
        ".reg .pred P1;\n\t"
        "W_%=:\n\t"
        "mbarrier.try_wait.parity.acquire.cta.shared::cta.b64 P1, [%0], 0, 0x989680;\n\t"
        "@P1 bra D_%=;\n\t"
        "bra W_%=;\n\t"
        "D_%=:\n\t"
        "}" :: "r"(mbar) : "memory");

    // ---- L0 fused SINGLE-PASS softmax + aggregate + BN0 + relu ----
    {
        const int hh = lane >> 3;
        const int pi = lane & 7;
        const int l4 = lane * 4;
        float4 sc = *(const float4*)(sscale + l4);
        float4 bs = *(const float4*)(sbias + l4);
        for (int d = wid; d < NNODE; d += 16) {
            const int beg = sptr[d], end = sptr[d + 1];
            const float sd = s_d[d * 4 + hh];
            float sum = 0.0f;
            for (int p = beg + pi; p < end; p += 8) {
                float e = s_s[(scsr[p] << 2) + hh] + sd;
                e = (e > 0.0f) ? e : 0.2f * e;
                float ex = __expf(e);        // softmax shift-invariant; |e| small
                sex[(p << 2) + hh] = ex;
                sum += ex;
            }
#pragma unroll
            for (int o = 4; o; o >>= 1)
                sum += __shfl_xor_sync(0xffffffffu, sum, o);
            const float rv = 1.0f / sum;

            // pipelined aggregate (>=1 edge guaranteed: self loop)
            float4 acc = make_float4(0.f, 0.f, 0.f, 0.f);
            int p = beg;
            float wv = sex[(p << 2) + hh];
            float4 v = *(const float4*)(sxh + (scsr[p] << 7) + l4);
            for (++p; p < end; ++p) {
                float wn = sex[(p << 2) + hh];
                float4 vn = *(const float4*)(sxh + (scsr[p] << 7) + l4);
                acc.x = fmaf(wv, v.x, acc.x);
                acc.y = fmaf(wv, v.y, acc.y);
                acc.z = fmaf(wv, v.z, acc.z);
                acc.w = fmaf(wv, v.w, acc.w);
                wv = wn; v = vn;
            }
            acc.x = fmaf(wv, v.x, acc.x);
            acc.y = fmaf(wv, v.y, acc.y);
            acc.z = fmaf(wv, v.z, acc.z);
            acc.w = fmaf(wv, v.w, acc.w);

            float4 r;
            r.x = fmaxf(fmaf(acc.x * rv, sc.x, bs.x), 0.0f);
            r.y = fmaxf(fmaf(acc.y * rv, sc.y, bs.y), 0.0f);
            r.z = fmaxf(fmaf(acc.z * rv, sc.z, bs.z), 0.0f);
            r.w = fmaxf(fmaf(acc.w * rv, sc.w, bs.w), 0.0f);
            *(float4*)(sh + d * HFEAT + l4) = r;
        }
    }
    __syncthreads();

    // restage L1 attention + BN1 fold
    if (tid < 128) {
        float sc = bn1g[tid] * rsqrtf(bn1v[tid] + 1e-5f);
        sscale[tid] = sc;
        sbias[tid]  = fmaf(g1b[tid] - bn1m[tid], sc, bn1b[tid]);
        satt[tid]       = g1as[tid];
        satt[128 + tid] = g1ad[tid];
    }

    // ==================== GAT layer 1 GEMM ====================
    gemm_sk(sh, sW, sxh, tid);
    __syncthreads();

    // ---- L1 scores: warp per node, full 32-lane reduce ----
    {
        float4 a1 = *(const float4*)(satt + lane * 4);
        float4 a2 = *(const float4*)(satt + 128 + lane * 4);
        for (int nd = wid; nd < NNODE; nd += 16) {
            float4 v = *(const float4*)(sxh + nd * HFEAT + lane * 4);
            float ss = v.x*a1.x + v.y*a1.y + v.z*a1.z + v.w*a1.w;
            float dd = v.x*a2.x + v.y*a2.y + v.z*a2.z + v.w*a2.w;
#pragma unroll
            for (int o = 16; o; o >>= 1) {
                ss += __shfl_xor_sync(0xffffffffu, ss, o);
                dd += __shfl_xor_sync(0xffffffffu, dd, o);
            }
            if (lane == 0) { s_s[nd] = ss; s_d[nd] = dd; }
        }
    }
    __syncthreads();

    // ---- L1 fused SINGLE-PASS softmax + aggregate + BN1 + relu + POOL ----
    {
        const int l4 = lane * 4;
        float4 sc = *(const float4*)(sscale + l4);
        float4 bs = *(const float4*)(sbias + l4);
        float4 pacc = make_float4(0.f, 0.f, 0.f, 0.f);
        for (int d = wid; d < NNODE; d += 16) {
            const int beg = sptr[d], end = sptr[d + 1];
            const float sd = s_d[d];
            float sum = 0.0f;
            for (int p = beg + lane; p < end; p += 32) {
                float e = s_s[scsr[p]] + sd;
                e = (e > 0.0f) ? e : 0.2f * e;
                float ex = __expf(e);
                sex[p] = ex;
                sum += ex;
            }
#pragma unroll
            for (int o = 16; o; o >>= 1)
                sum += __shfl_xor_sync(0xffffffffu, sum, o);
            const float rv = 1.0f / sum;

            float4 acc = make_float4(0.f, 0.f, 0.f, 0.f);
            int p = beg;
            float wv = sex[p];
            float4 v = *(const float4*)(sxh + (scsr[p] << 7) + l4);
            for (++p; p < end; ++p) {
                float wn = sex[p];
                float4 vn = *(const float4*)(sxh + (scsr[p] << 7) + l4);
                acc.x = fmaf(wv, v.x, acc.x);
                acc.y = fmaf(wv, v.y, acc.y);
                acc.z = fmaf(wv, v.z, acc.z);
                acc.w = fmaf(wv, v.w, acc.w);
                wv = wn; v = vn;
            }
            acc.x = fmaf(wv, v.x, acc.x);
            acc.y = fmaf(wv, v.y, acc.y);
            acc.z = fmaf(wv, v.z, acc.z);
            acc.w = fmaf(wv, v.w, acc.w);

            pacc.x += fmaxf(fmaf(acc.x * rv, sc.x, bs.x), 0.0f);
            pacc.y += fmaxf(fmaf(acc.y * rv, sc.y, bs.y), 0.0f);
            pacc.z += fmaxf(fmaf(acc.z * rv, sc.z, bs.z), 0.0f);
            pacc.w += fmaxf(fmaf(acc.w * rv, sc.w, bs.w), 0.0f);
        }
        *(float4*)(sh + wid * HFEAT + l4) = pacc;   // per-warp pool partial
    }
    __syncthreads();

    // ---- pool reduce ----
    if (tid < 128) {
        float acc = 0.0f;
#pragma unroll
        for (int w = 0; w < 16; ++w) acc += sh[w * HFEAT + tid];
        hp[tid] = acc * (1.0f / 128.0f);
    }
    __syncthreads();

    // ---- MLP ----
    if (tid < 64) {
        float acc = b1[tid];
#pragma unroll 8
        for (int f = 0; f < 128; ++f) acc = fmaf(hp[f], w1[f * 64 + tid], acc);
        zz[tid] = fmaxf(acc, 0.0f);
    }
    __syncthreads();
    if (tid == 0) {
        float acc = b2[0];
#pragma unroll
        for (int j = 0; j < 64; ++j) acc = fmaf(zz[j], w2[j], acc);
        out[b] = acc;
    }
}

// ---------------------------------------------------------------------------
extern "C" void kernel_launch(void* const* d_in, const int* in_sizes, int n_in,
                              void* d_out, int out_size) {
    (void)in_sizes; (void)n_in; (void)out_size;
    const float* x    = (const float*)d_in[0];
    const int*   ei   = (const int*)d_in[1];
    const float* w_in = (const float*)d_in[2];
    const float* b_in = (const float*)d_in[3];
    const float* g0w  = (const float*)d_in[4];
    const float* g0as = (const float*)d_in[5];
    const float* g0ad = (const float*)d_in[6];
    const float* g0b  = (const float*)d_in[7];
    const float* bn0g = (const float*)d_in[8];
    const float* bn0b = (const float*)d_in[9];
    const float* bn0m = (const float*)d_in[10];
    const float* bn0v = (const float*)d_in[11];
    const float* g1w  = (const float*)d_in[12];
    const float* g1as = (const float*)d_in[13];
    const float* g1ad = (const float*)d_in[14];
    const float* g1b  = (const float*)d_in[15];
    const float* bn1g = (const float*)d_in[16];
    const float* bn1b = (const float*)d_in[17];
    const float* bn1m = (const float*)d_in[18];
    const float* bn1v = (const float*)d_in[19];
    const float* w1   = (const float*)d_in[20];
    const float* b1   = (const float*)d_in[21];
    const float* w2   = (const float*)d_in[22];
    const float* b2   = (const float*)d_in[23];
    float* out = (float*)d_out;

    cudaFuncSetAttribute(gnn_kernel,
                         cudaFuncAttributeMaxDynamicSharedMemorySize, SMEM_BYTES);

    setup_kernel<<<2, 1024>>>(ei, w_in, b_in, g0w);
    gnn_kernel<<<NGRAPH, NTHREADS, SMEM_BYTES>>>(
        x, g0as, g0ad, g0b, bn0g, bn0b, bn0m, bn0v,
        g1w, g1as, g1ad, g1b, bn1g, bn1b, bn1m, bn1v,
        w1, b1, w2, b2, out);
}

// round 13
// speedup vs baseline: 1.1273x; 1.0238x over previous
#include <cuda_runtime.h>

#define NNODE  128
#define NEDGE  1024
#define ETOT   1152
#define HFEAT  128
#define NGRAPH 1024
#define NTHREADS 512

// ---------------------------------------------------------------------------
// Device-global setup state (rebuilt every launch; deterministic).
// ---------------------------------------------------------------------------
__device__ __align__(16) int   g_csr_ptr[132];            // 129 used, padded
__device__ __align__(16) int   g_csr_src[ETOT];
__device__ __align__(16) int   g_sord[NNODE];             // snake node order
__device__ __align__(16) float g_t[HFEAT];                // sorted breakpoints
__device__ __align__(16) float g_A[(HFEAT + 1) * HFEAT];  // interval slopes
__device__ __align__(16) float g_B[(HFEAT + 1) * HFEAT];  // interval offsets

// ---------------------------------------------------------------------------
// Combined setup: block 0 = CSR + degree-snake order, block 1 = PWL tables.
// ---------------------------------------------------------------------------
__global__ void setup_kernel(const int* __restrict__ ei,
                             const float* __restrict__ w_in,
                             const float* __restrict__ b_in,
                             const float* __restrict__ W) {
    if (blockIdx.x == 0) {
        __shared__ int s_src[NEDGE];
        __shared__ int s_dst[NEDGE];
        __shared__ int hist[32][NNODE];
        __shared__ int cnt[NNODE];
        __shared__ int base[NNODE + 1];
        const int t = threadIdx.x;
        const int w = t >> 5, l = t & 31;
        s_src[t] = ei[t];
        s_dst[t] = ei[NEDGE + t];
        for (int i = t; i < 32 * NNODE; i += 1024) ((int*)hist)[i] = 0;
        __syncthreads();
        const int d = s_dst[t];
        unsigned mask = __match_any_sync(0xffffffffu, d);
        int lane_rank = __popc(mask & ((1u << l) - 1u));
        if (l == (__ffs(mask) - 1)) hist[w][d] = __popc(mask);
        __syncthreads();
        if (t < NNODE) {
            int acc = 0;
#pragma unroll
            for (int c = 0; c < 32; ++c) {
                int v = hist[c][t];
                hist[c][t] = acc;
                acc += v;
            }
            cnt[t] = acc;
        }
        __syncthreads();
        if (t == 0) {
            int acc = 0;
            for (int dd = 0; dd < NNODE; ++dd) { base[dd] = acc; acc += cnt[dd] + 1; }
            base[NNODE] = acc;
        }
        __syncthreads();
        if (t <= NNODE) g_csr_ptr[t] = base[t];
        g_csr_src[base[d] + hist[w][d] + lane_rank] = s_src[t];
        if (t < NNODE) g_csr_src[base[t] + cnt[t]] = t;   // self loop last
        // degree-sorted snake assignment: rank nodes by degree (desc), snake
        // over 16 warps so each warp's total edge count is balanced.
        if (t < NNODE) {
            int ct = cnt[t];
            int r = 0;
            for (int g = 0; g < NNODE; ++g) {
                int cg = cnt[g];
                r += (cg > ct) || (cg == ct && g < t);
            }
            int it = r >> 4, pos = r & 15;
            int wdst = (it & 1) ? (15 - pos) : pos;
            g_sord[(it << 4) + wdst] = t;
        }
    } else {
        __shared__ float sw[HFEAT], sb[HFEAT], st[HFEAT];
        __shared__ int   ord[HFEAT];
        const int t = threadIdx.x;
        if (t >= HFEAT) return;
        sw[t] = w_in[t];
        sb[t] = b_in[t];
        __syncthreads();
        const float wf = sw[t], bf = sb[t];
        const float INF = __int_as_float(0x7f800000);
        float tf = (wf == 0.0f) ? INF : (-bf / wf);
        st[t] = tf;
        __syncthreads();
        tf = st[t];
        int rank = 0;
        for (int g = 0; g < HFEAT; ++g) {
            float tg = st[g];
            rank += (tg < tf) || (tg == tf && g < t);
        }
        ord[rank] = t;
        __syncthreads();
        g_t[t] = st[ord[t]];

        const int c = t;
        float A = 0.0f, B = 0.0f;
        for (int f = 0; f < HFEAT; ++f) {
            float Wfc = W[f * HFEAT + c];
            float w = sw[f];
            if (w < 0.0f)                       { A += w * Wfc; B += sb[f] * Wfc; }
            else if (w == 0.0f && sb[f] > 0.0f) { B += sb[f] * Wfc; }
        }
        g_A[c] = A; g_B[c] = B;
        for (int j = 0; j < HFEAT; ++j) {
            int f = ord[j];
            float w = sw[f];
            float Wfc = W[f * HFEAT + c];
            if (w > 0.0f)      { A += w * Wfc; B += sb[f] * Wfc; }
            else if (w < 0.0f) { A -= w * Wfc; B -= sb[f] * Wfc; }
            g_A[(j + 1) * HFEAT + c] = A;
            g_B[(j + 1) * HFEAT + c] = B;
        }
    }
}

// ---------------------------------------------------------------------------
// Shared memory layout (floats). sW/sptr/scsr filled by cp.async.bulk.
// ---------------------------------------------------------------------------
constexpr int OFF_SH    = 0;
constexpr int OFF_SXH   = OFF_SH  + NNODE * HFEAT;       // 16384
constexpr int OFF_SW    = OFF_SXH + NNODE * HFEAT;       // 16384
constexpr int OFF_SEX   = OFF_SW  + HFEAT * HFEAT;       // 4608
constexpr int OFF_SS    = OFF_SEX + ETOT * 4;            // 512
constexpr int OFF_SD    = OFF_SS  + 512;                 // 512
constexpr int OFF_SATT  = OFF_SD  + 512;                 // 256
constexpr int OFF_SCALE = OFF_SATT + 256;                // 128
constexpr int OFF_BIAS  = OFF_SCALE + 128;               // 128
constexpr int OFF_HP    = OFF_BIAS + 128;                // 128
constexpr int OFF_ZZ    = OFF_HP + 128;                  // 64
constexpr int OFF_XV    = OFF_ZZ + 64;                   // 128
constexpr int OFF_ST    = OFF_XV + 128;                  // 128 (staged g_t)
constexpr int OFF_MBAR  = OFF_ST + 128;                  // 4
constexpr int SM_FLOATS = OFF_MBAR + 4;
constexpr int SM_INTS   = 132 + ETOT + 128;              // +sdord
constexpr int SMEM_BYTES = SM_FLOATS * 4 + SM_INTS * 4;  // 228640 B

constexpr int TX_BYTES = 132 * 4 + ETOT * 4 + HFEAT * HFEAT * 4;  // 70672

// ---------------------------------------------------------------------------
// Packed fp32x2 helpers (f32x2 ops are PTX-only)
// ---------------------------------------------------------------------------
__device__ __forceinline__ unsigned long long pack2(float a) {
    unsigned long long r;
    unsigned int ai = __float_as_uint(a);
    asm("mov.b64 %0, {%1, %1};" : "=l"(r) : "r"(ai));
    return r;
}
__device__ __forceinline__ void ffma2(unsigned long long& d,
                                      unsigned long long a,
                                      unsigned long long b) {
    asm("fma.rn.f32x2 %0, %1, %2, %0;" : "+l"(d) : "l"(a), "l"(b));
}
__device__ __forceinline__ void fadd2(unsigned long long& d,
                                      unsigned long long a) {
    asm("add.rn.f32x2 %0, %0, %1;" : "+l"(d) : "l"(a));
}

// ---------------------------------------------------------------------------
// Split-K GEMM: C = A @ W, all SMEM, 16 warps, 8x8 thread tiles.
// One internal __syncthreads(); all 512 threads must call.
// ---------------------------------------------------------------------------
__device__ __forceinline__ void gemm_sk(const float* __restrict__ A,
                                        const float* __restrict__ sW,
                                        float* __restrict__ C, int tid) {
    const int w  = tid >> 5;
    const int l  = tid & 31;
    const int kh = w >> 3;
    const int r0 = (w & 7) * 16 + (l >> 4) * 8;
    const int ca = (l & 15) * 4;
    const int k0 = kh * 64;

    unsigned long long acc[8][4];
#pragma unroll
    for (int i = 0; i < 8; ++i)
#pragma unroll
        for (int j = 0; j < 4; ++j) acc[i][j] = 0ull;

#pragma unroll 4
    for (int k = k0; k < k0 + 64; k += 2) {
        float2 a[8];
#pragma unroll
        for (int i = 0; i < 8; ++i)
            a[i] = *(const float2*)(A + (r0 + i) * HFEAT + k);
        ulonglong2 w00 = *(const ulonglong2*)(sW + k * HFEAT + ca);
        ulonglong2 w01 = *(const ulonglong2*)(sW + k * HFEAT + ca + 64);
        ulonglong2 w10 = *(const ulonglong2*)(sW + (k + 1) * HFEAT + ca);
        ulonglong2 w11 = *(const ulonglong2*)(sW + (k + 1) * HFEAT + ca + 64);
#pragma unroll
        for (int i = 0; i < 8; ++i) {
            unsigned long long ax = pack2(a[i].x);
            unsigned long long ay = pack2(a[i].y);
            ffma2(acc[i][0], ax, w00.x);
            ffma2(acc[i][1], ax, w00.y);
            ffma2(acc[i][2], ax, w01.x);
            ffma2(acc[i][3], ax, w01.y);
            ffma2(acc[i][0], ay, w10.x);
            ffma2(acc[i][1], ay, w10.y);
            ffma2(acc[i][2], ay, w11.x);
            ffma2(acc[i][3], ay, w11.y);
        }
    }

    if (kh == 1) {
#pragma unroll
        for (int i = 0; i < 8; ++i) {
            ulonglong2 s0, s1;
            s0.x = acc[i][0]; s0.y = acc[i][1];
            s1.x = acc[i][2]; s1.y = acc[i][3];
            *(ulonglong2*)(C + (r0 + i) * HFEAT + ca)      = s0;
            *(ulonglong2*)(C + (r0 + i) * HFEAT + ca + 64) = s1;
        }
    }
    __syncthreads();
    if (kh == 0) {
#pragma unroll
        for (int i = 0; i < 8; ++i) {
            ulonglong2 p0 = *(const ulonglong2*)(C + (r0 + i) * HFEAT + ca);
            ulonglong2 p1 = *(const ulonglong2*)(C + (r0 + i) * HFEAT + ca + 64);
            fadd2(acc[i][0], p0.x);
            fadd2(acc[i][1], p0.y);
            fadd2(acc[i][2], p1.x);
            fadd2(acc[i][3], p1.y);
            ulonglong2 s0, s1;
            s0.x = acc[i][0]; s0.y = acc[i][1];
            s1.x = acc[i][2]; s1.y = acc[i][3];
            *(ulonglong2*)(C + (r0 + i) * HFEAT + ca)      = s0;
            *(ulonglong2*)(C + (r0 + i) * HFEAT + ca + 64) = s1;
        }
    }
}

__global__ __launch_bounds__(NTHREADS, 1)
void gnn_kernel(const float* __restrict__ x,
                const float* __restrict__ g0as, const float* __restrict__ g0ad,
                const float* __restrict__ g0b,
                const float* __restrict__ bn0g, const float* __restrict__ bn0b,
                const float* __restrict__ bn0m, const float* __restrict__ bn0v,
                const float* __restrict__ g1w, const float* __restrict__ g1as,
                const float* __restrict__ g1ad, const float* __restrict__ g1b,
                const float* __restrict__ bn1g, const float* __restrict__ bn1b,
                const float* __restrict__ bn1m, const float* __restrict__ bn1v,
                const float* __restrict__ w1, const float* __restrict__ b1,
                const float* __restrict__ w2, const float* __restrict__ b2,
                float* __restrict__ out) {
    extern __shared__ float smem[];
    float* sh    = smem + OFF_SH;     // L0 output; later: pool partials
    float* sxh   = smem + OFF_SXH;
    float* sW    = smem + OFF_SW;
    float* sex   = smem + OFF_SEX;
    float* s_s   = smem + OFF_SS;
    float* s_d   = smem + OFF_SD;
    float* satt  = smem + OFF_SATT;
    float* sscale= smem + OFF_SCALE;
    float* sbias = smem + OFF_BIAS;
    float* hp    = smem + OFF_HP;
    float* zz    = smem + OFF_ZZ;
    float* sxv   = smem + OFF_XV;
    float* st    = smem + OFF_ST;
    int*   sptr  = (int*)(smem + SM_FLOATS);
    int*   scsr  = sptr + 132;
    int*   sdord = scsr + ETOT;

    const int tid  = threadIdx.x;
    const int wid  = tid >> 5;
    const int lane = tid & 31;
    const int b    = blockIdx.x;
    const unsigned mbar = (unsigned)__cvta_generic_to_shared(smem + OFF_MBAR);

    // ---- init ----
    if (tid == 0)
        asm volatile("mbarrier.init.shared.b64 [%0], %1;" :: "r"(mbar), "r"(1) : "memory");
    if (tid < 128) {
        satt[tid]       = g0as[tid];
        satt[128 + tid] = g0ad[tid];
        float sc = bn0g[tid] * rsqrtf(bn0v[tid] + 1e-5f);
        sscale[tid] = sc;
        sbias[tid]  = fmaf(g0b[tid] - bn0m[tid], sc, bn0b[tid]);
        sxv[tid]   = x[b * NNODE + tid];
        st[tid]    = g_t[tid];
        sdord[tid] = g_sord[tid];
    }
    __syncthreads();

    // async loads: CSR (ptr+src) + W1; land before the L0 softmax wait
    if (tid == 0) {
        unsigned a_sw   = (unsigned)__cvta_generic_to_shared(sW);
        unsigned a_sptr = (unsigned)__cvta_generic_to_shared(sptr);
        unsigned a_scsr = (unsigned)__cvta_generic_to_shared(scsr);
        asm volatile("mbarrier.arrive.expect_tx.shared.b64 _, [%0], %1;"
                     :: "r"(mbar), "r"(TX_BYTES) : "memory");
        asm volatile("cp.async.bulk.shared::cta.global.mbarrier::complete_tx::bytes "
                     "[%0], [%1], %2, [%3];"
                     :: "r"(a_sw), "l"(g1w), "r"(HFEAT * HFEAT * 4), "r"(mbar) : "memory");
        asm volatile("cp.async.bulk.shared::cta.global.mbarrier::complete_tx::bytes "
                     "[%0], [%1], %2, [%3];"
                     :: "r"(a_sptr), "l"(g_csr_ptr), "r"(132 * 4), "r"(mbar) : "memory");
        asm volatile("cp.async.bulk.shared::cta.global.mbarrier::complete_tx::bytes "
                     "[%0], [%1], %2, [%3];"
                     :: "r"(a_scsr), "l"(g_csr_src), "r"(ETOT * 4), "r"(mbar) : "memory");
    }

    // ---- xh0 = x*A_j + B_j (PWL) with fused L0 scores, batch-4 prefetch ----
    {
        float4 a1 = *(const float4*)(satt + lane * 4);
        float4 a2 = *(const float4*)(satt + 128 + lane * 4);
        const int l4 = lane * 4;
#pragma unroll
        for (int base = 0; base < 8; base += 4) {
            float xvv[4];
            float4 Av[4], Bv[4];
#pragma unroll
            for (int q = 0; q < 4; ++q) {           // issue all 8 loads (MLP=8)
                int n = wid + ((base + q) << 4);
                float xv = sxv[n];
                xvv[q] = xv;
                int j = 0;
#pragma unroll
                for (int r = 0; r < 4; ++r)
                    j += __popc(__ballot_sync(0xffffffffu, st[lane + 32 * r] <= xv));
                Av[q] = *(const float4*)(g_A + j * HFEAT + l4);
                Bv[q] = *(const float4*)(g_B + j * HFEAT + l4);
            }
#pragma unroll
            for (int q = 0; q < 4; ++q) {
                int n = wid + ((base + q) << 4);
                float xv = xvv[q];
                float4 v;
                v.x = fmaf(xv, Av[q].x, Bv[q].x);
                v.y = fmaf(xv, Av[q].y, Bv[q].y);
                v.z = fmaf(xv, Av[q].z, Bv[q].z);
                v.w = fmaf(xv, Av[q].w, Bv[q].w);
                *(float4*)(sxh + n * HFEAT + l4) = v;
                float ss = v.x*a1.x + v.y*a1.y + v.z*a1.z + v.w*a1.w;
                float dd = v.x*a2.x + v.y*a2.y + v.z*a2.z + v.w*a2.w;
#pragma unroll
                for (int o = 4; o; o >>= 1) {
                    ss += __shfl_xor_sync(0xffffffffu, ss, o);
                    dd += __shfl_xor_sync(0xffffffffu, dd, o);
                }
                if ((lane & 7) == 0) {
                    s_s[n * 4 + (lane >> 3)] = ss;
                    s_d[n * 4 + (lane >> 3)] = dd;
                }
            }
        }
    }
    __syncthreads();

    // wait for async CSR + W1 (all threads)
    asm volatile(
        "{\n\t"
        ".reg .pred P1;\n\t"
        "W_%=:\n\t"
        "mbarrier.try_wait.parity.acquire.cta.shared::cta.b64 P1, [%0], 0, 0x989680;\n\t"
        "@P1 bra D_%=;\n\t"
        "bra W_%=;\n\t"
        "D_%=:\n\t"
        "}" :: "r"(mbar) : "memory");

    // ---- L0 fused single-pass softmax + aggregate + BN0 + relu ----
    {
        const int hh = lane >> 3;
        const int pi = lane & 7;
        const int l4 = lane * 4;
        float4 sc = *(const float4*)(sscale + l4);
        float4 bs = *(const float4*)(sbias + l4);
#pragma unroll
        for (int it = 0; it < 8; ++it) {
            const int d = sdord[(it << 4) + wid];   // degree-balanced order
            const int beg = sptr[d], end = sptr[d + 1];
            const float sd = s_d[d * 4 + hh];
            float sum = 0.0f;
            for (int p = beg + pi; p < end; p += 8) {
                float e = s_s[(scsr[p] << 2) + hh] + sd;
                e = (e > 0.0f) ? e : 0.2f * e;
                float ex = __expf(e);        // softmax shift-invariant; |e| small
                sex[(p << 2) + hh] = ex;
                sum += ex;
            }
#pragma unroll
            for (int o = 4; o; o >>= 1)
                sum += __shfl_xor_sync(0xffffffffu, sum, o);
            const float rv = 1.0f / sum;

            float4 acc = make_float4(0.f, 0.f, 0.f, 0.f);
            int p = beg;
            float wv = sex[(p << 2) + hh];
            float4 v = *(const float4*)(sxh + (scsr[p] << 7) + l4);
            for (++p; p < end; ++p) {
                float wn = sex[(p << 2) + hh];
                float4 vn = *(const float4*)(sxh + (scsr[p] << 7) + l4);
                acc.x = fmaf(wv, v.x, acc.x);
                acc.y = fmaf(wv, v.y, acc.y);
                acc.z = fmaf(wv, v.z, acc.z);
                acc.w = fmaf(wv, v.w, acc.w);
                wv = wn; v = vn;
            }
            acc.x = fmaf(wv, v.x, acc.x);
            acc.y = fmaf(wv, v.y, acc.y);
            acc.z = fmaf(wv, v.z, acc.z);
            acc.w = fmaf(wv, v.w, acc.w);

            float4 r;
            r.x = fmaxf(fmaf(acc.x * rv, sc.x, bs.x), 0.0f);
            r.y = fmaxf(fmaf(acc.y * rv, sc.y, bs.y), 0.0f);
            r.z = fmaxf(fmaf(acc.z * rv, sc.z, bs.z), 0.0f);
            r.w = fmaxf(fmaf(acc.w * rv, sc.w, bs.w), 0.0f);
            *(float4*)(sh + d * HFEAT + l4) = r;
        }
    }
    __syncthreads();

    // restage L1 attention + BN1 fold
    if (tid < 128) {
        float sc = bn1g[tid] * rsqrtf(bn1v[tid] + 1e-5f);
        sscale[tid] = sc;
        sbias[tid]  = fmaf(g1b[tid] - bn1m[tid], sc, bn1b[tid]);
        satt[tid]       = g1as[tid];
        satt[128 + tid] = g1ad[tid];
    }

    // ==================== GAT layer 1 GEMM ====================
    gemm_sk(sh, sW, sxh, tid);
    __syncthreads();

    // ---- L1 scores: warp per node, full 32-lane reduce ----
    {
        float4 a1 = *(const float4*)(satt + lane * 4);
        float4 a2 = *(const float4*)(satt + 128 + lane * 4);
        for (int nd = wid; nd < NNODE; nd += 16) {
            float4 v = *(const float4*)(sxh + nd * HFEAT + lane * 4);
            float ss = v.x*a1.x + v.y*a1.y + v.z*a1.z + v.w*a1.w;
            float dd = v.x*a2.x + v.y*a2.y + v.z*a2.z + v.w*a2.w;
#pragma unroll
            for (int o = 16; o; o >>= 1) {
                ss += __shfl_xor_sync(0xffffffffu, ss, o);
                dd += __shfl_xor_sync(0xffffffffu, dd, o);
            }
            if (lane == 0) { s_s[nd] = ss; s_d[nd] = dd; }
        }
    }
    __syncthreads();

    // ---- L1 fused single-pass softmax + aggregate + BN1 + relu + POOL ----
    {
        const int l4 = lane * 4;
        float4 sc = *(const float4*)(sscale + l4);
        float4 bs = *(const float4*)(sbias + l4);
        float4 pacc = make_float4(0.f, 0.f, 0.f, 0.f);
#pragma unroll
        for (int it = 0; it < 8; ++it) {
            const int d = sdord[(it << 4) + wid];   // degree-balanced order
            const int beg = sptr[d], end = sptr[d + 1];
            const float sd = s_d[d];
            float sum = 0.0f;
            for (int p = beg + lane; p < end; p += 32) {
                float e = s_s[scsr[p]] + sd;
                e = (e > 0.0f) ? e : 0.2f * e;
                float ex = __expf(e);
                sex[p] = ex;
                sum += ex;
            }
#pragma unroll
            for (int o = 16; o; o >>= 1)
                sum += __shfl_xor_sync(0xffffffffu, sum, o);
            const float rv = 1.0f / sum;

            float4 acc = make_float4(0.f, 0.f, 0.f, 0.f);
            int p = beg;
            float wv = sex[p];
            float4 v = *(const float4*)(sxh + (scsr[p] << 7) + l4);
            for (++p; p < end; ++p) {
                float wn = sex[p];
                float4 vn = *(const float4*)(sxh + (scsr[p] << 7) + l4);
                acc.x = fmaf(wv, v.x, acc.x);
                acc.y = fmaf(wv, v.y, acc.y);
                acc.z = fmaf(wv, v.z, acc.z);
                acc.w = fmaf(wv, v.w, acc.w);
                wv = wn; v = vn;
            }
            acc.x = fmaf(wv, v.x, acc.x);
            acc.y = fmaf(wv, v.y, acc.y);
            acc.z = fmaf(wv, v.z, acc.z);
            acc.w = fmaf(wv, v.w, acc.w);

            pacc.x += fmaxf(fmaf(acc.x * rv, sc.x, bs.x), 0.0f);
            pacc.y += fmaxf(fmaf(acc.y * rv, sc.y, bs.y), 0.0f);
            pacc.z += fmaxf(fmaf(acc.z * rv, sc.z, bs.z), 0.0f);
            pacc.w += fmaxf(fmaf(acc.w * rv, sc.w, bs.w), 0.0f);
        }
        *(float4*)(sh + wid * HFEAT + l4) = pacc;   // per-warp pool partial
    }
    __syncthreads();

    // ---- pool reduce ----
    if (tid < 128) {
        float acc = 0.0f;
#pragma unroll
        for (int w = 0; w < 16; ++w) acc += sh[w * HFEAT + tid];
        hp[tid] = acc * (1.0f / 128.0f);
    }
    __syncthreads();

    // ---- MLP ----
    if (tid < 64) {
        float acc = b1[tid];
#pragma unroll 8
        for (int f = 0; f < 128; ++f) acc = fmaf(hp[f], w1[f * 64 + tid], acc);
        zz[tid] = fmaxf(acc, 0.0f);
    }
    __syncthreads();
    if (tid == 0) {
        float acc = b2[0];
#pragma unroll
        for (int j = 0; j < 64; ++j) acc = fmaf(zz[j], w2[j], acc);
        out[b] = acc;
    }
}

// ---------------------------------------------------------------------------
extern "C" void kernel_launch(void* const* d_in, const int* in_sizes, int n_in,
                              void* d_out, int out_size) {
    (void)in_sizes; (void)n_in; (void)out_size;
    const float* x    = (const float*)d_in[0];
    const int*   ei   = (const int*)d_in[1];
    const float* w_in = (const float*)d_in[2];
    const float* b_in = (const float*)d_in[3];
    const float* g0w  = (const float*)d_in[4];
    const float* g0as = (const float*)d_in[5];
    const float* g0ad = (const float*)d_in[6];
    const float* g0b  = (const float*)d_in[7];
    const float* bn0g = (const float*)d_in[8];
    const float* bn0b = (const float*)d_in[9];
    const float* bn0m = (const float*)d_in[10];
    const float* bn0v = (const float*)d_in[11];
    const float* g1w  = (const float*)d_in[12];
    const float* g1as = (const float*)d_in[13];
    const float* g1ad = (const float*)d_in[14];
    const float* g1b  = (const float*)d_in[15];
    const float* bn1g = (const float*)d_in[16];
    const float* bn1b = (const float*)d_in[17];
    const float* bn1m = (const float*)d_in[18];
    const float* bn1v = (const float*)d_in[19];
    const float* w1   = (const float*)d_in[20];
    const float* b1   = (const float*)d_in[21];
    const float* w2   = (const float*)d_in[22];
    const float* b2   = (const float*)d_in[23];
    float* out = (float*)d_out;

    cudaFuncSetAttribute(gnn_kernel,
                         cudaFuncAttributeMaxDynamicSharedMemorySize, SMEM_BYTES);

    setup_kernel<<<2, 1024>>>(ei, w_in, b_in, g0w);
    gnn_kernel<<<NGRAPH, NTHREADS, SMEM_BYTES>>>(
        x, g0as, g0ad, g0b, bn0g, bn0b, bn0m, bn0v,
        g1w, g1as, g1ad, g1b, bn1g, bn1b, bn1m, bn1v,
        w1, b1, w2, b2, out);
}

// round 14
// speedup vs baseline: 1.1477x; 1.0182x over previous
#include <cuda_runtime.h>

#define NNODE  128
#define NEDGE  1024
#define ETOT   1152
#define HFEAT  128
#define NGRAPH 1024
#define NTHREADS 512

// ---------------------------------------------------------------------------
// Device-global setup state (rebuilt every launch; deterministic).
// ---------------------------------------------------------------------------
__device__ __align__(16) int   g_csr_ptr[132];            // 129 used, padded
__device__ __align__(16) int   g_csr_src[ETOT];
__device__ __align__(16) int   g_sord[NNODE];             // snake node order
__device__ __align__(16) float g_t[HFEAT];                // sorted breakpoints
__device__ __align__(16) float g_A[(HFEAT + 1) * HFEAT];  // interval slopes
__device__ __align__(16) float g_B[(HFEAT + 1) * HFEAT];  // interval offsets

// ---------------------------------------------------------------------------
// Combined setup: block 0 = CSR + degree-snake order, block 1 = PWL tables.
// ---------------------------------------------------------------------------
__global__ void setup_kernel(const int* __restrict__ ei,
                             const float* __restrict__ w_in,
                             const float* __restrict__ b_in,
                             const float* __restrict__ W) {
    if (blockIdx.x == 0) {
        __shared__ int s_src[NEDGE];
        __shared__ int s_dst[NEDGE];
        __shared__ int hist[32][NNODE];
        __shared__ int cnt[NNODE];
        __shared__ int base[NNODE + 1];
        const int t = threadIdx.x;
        const int w = t >> 5, l = t & 31;
        s_src[t] = ei[t];
        s_dst[t] = ei[NEDGE + t];
        for (int i = t; i < 32 * NNODE; i += 1024) ((int*)hist)[i] = 0;
        __syncthreads();
        const int d = s_dst[t];
        unsigned mask = __match_any_sync(0xffffffffu, d);
        int lane_rank = __popc(mask & ((1u << l) - 1u));
        if (l == (__ffs(mask) - 1)) hist[w][d] = __popc(mask);
        __syncthreads();
        if (t < NNODE) {
            int acc = 0;
#pragma unroll
            for (int c = 0; c < 32; ++c) {
                int v = hist[c][t];
                hist[c][t] = acc;
                acc += v;
            }
            cnt[t] = acc;
        }
        __syncthreads();
        if (t == 0) {
            int acc = 0;
            for (int dd = 0; dd < NNODE; ++dd) { base[dd] = acc; acc += cnt[dd] + 1; }
            base[NNODE] = acc;
        }
        __syncthreads();
        if (t <= NNODE) g_csr_ptr[t] = base[t];
        g_csr_src[base[d] + hist[w][d] + lane_rank] = s_src[t];
        if (t < NNODE) g_csr_src[base[t] + cnt[t]] = t;   // self loop last
        // degree-sorted snake assignment over 16 warps
        if (t < NNODE) {
            int ct = cnt[t];
            int r = 0;
            for (int g = 0; g < NNODE; ++g) {
                int cg = cnt[g];
                r += (cg > ct) || (cg == ct && g < t);
            }
            int it = r >> 4, pos = r & 15;
            int wdst = (it & 1) ? (15 - pos) : pos;
            g_sord[(it << 4) + wdst] = t;
        }
    } else {
        __shared__ float sw[HFEAT], sb[HFEAT], st[HFEAT];
        __shared__ int   ord[HFEAT];
        const int t = threadIdx.x;
        if (t >= HFEAT) return;
        sw[t] = w_in[t];
        sb[t] = b_in[t];
        __syncthreads();
        const float wf = sw[t], bf = sb[t];
        const float INF = __int_as_float(0x7f800000);
        float tf = (wf == 0.0f) ? INF : (-bf / wf);
        st[t] = tf;
        __syncthreads();
        tf = st[t];
        int rank = 0;
        for (int g = 0; g < HFEAT; ++g) {
            float tg = st[g];
            rank += (tg < tf) || (tg == tf && g < t);
        }
        ord[rank] = t;
        __syncthreads();
        g_t[t] = st[ord[t]];

        const int c = t;
        float A = 0.0f, B = 0.0f;
        for (int f = 0; f < HFEAT; ++f) {
            float Wfc = W[f * HFEAT + c];
            float w = sw[f];
            if (w < 0.0f)                       { A += w * Wfc; B += sb[f] * Wfc; }
            else if (w == 0.0f && sb[f] > 0.0f) { B += sb[f] * Wfc; }
        }
        g_A[c] = A; g_B[c] = B;
        for (int j = 0; j < HFEAT; ++j) {
            int f = ord[j];
            float w = sw[f];
            float Wfc = W[f * HFEAT + c];
            if (w > 0.0f)      { A += w * Wfc; B += sb[f] * Wfc; }
            else if (w < 0.0f) { A -= w * Wfc; B -= sb[f] * Wfc; }
            g_A[(j + 1) * HFEAT + c] = A;
            g_B[(j + 1) * HFEAT + c] = B;
        }
    }
}

// ---------------------------------------------------------------------------
// Shared memory layout (floats). sW/sptr/scsr filled by cp.async.bulk.
// ---------------------------------------------------------------------------
constexpr int OFF_SH    = 0;
constexpr int OFF_SXH   = OFF_SH  + NNODE * HFEAT;       // 16384
constexpr int OFF_SW    = OFF_SXH + NNODE * HFEAT;       // 16384
constexpr int OFF_SEX   = OFF_SW  + HFEAT * HFEAT;       // 4608
constexpr int OFF_SS    = OFF_SEX + ETOT * 4;            // 512
constexpr int OFF_SD    = OFF_SS  + 512;                 // 512
constexpr int OFF_SATT  = OFF_SD  + 512;                 // 256
constexpr int OFF_SCALE = OFF_SATT + 256;                // 128
constexpr int OFF_BIAS  = OFF_SCALE + 128;               // 128
constexpr int OFF_HP    = OFF_BIAS + 128;                // 128
constexpr int OFF_ZZ    = OFF_HP + 128;                  // 64
constexpr int OFF_XV    = OFF_ZZ + 64;                   // 128
constexpr int OFF_ST    = OFF_XV + 128;                  // 128 (staged g_t)
constexpr int OFF_MBAR  = OFF_ST + 128;                  // 4
constexpr int SM_FLOATS = OFF_MBAR + 4;
constexpr int SM_INTS   = 132 + ETOT + 128;              // +sdord
constexpr int SMEM_BYTES = SM_FLOATS * 4 + SM_INTS * 4;  // 228640 B

constexpr int TX_BYTES = 132 * 4 + ETOT * 4 + HFEAT * HFEAT * 4;  // 70672

// ---------------------------------------------------------------------------
// Packed fp32x2 helpers (f32x2 ops are PTX-only)
// ---------------------------------------------------------------------------
__device__ __forceinline__ unsigned long long pack2(float a) {
    unsigned long long r;
    unsigned int ai = __float_as_uint(a);
    asm("mov.b64 %0, {%1, %1};" : "=l"(r) : "r"(ai));
    return r;
}
__device__ __forceinline__ void ffma2(unsigned long long& d,
                                      unsigned long long a,
                                      unsigned long long b) {
    asm("fma.rn.f32x2 %0, %1, %2, %0;" : "+l"(d) : "l"(a), "l"(b));
}
__device__ __forceinline__ void fadd2(unsigned long long& d,
                                      unsigned long long a) {
    asm("add.rn.f32x2 %0, %0, %1;" : "+l"(d) : "l"(a));
}
__device__ __forceinline__ float2 unpk2(unsigned long long v) {
    float2 r;
    asm("mov.b64 {%0, %1}, %2;" : "=f"(r.x), "=f"(r.y) : "l"(v));
    return r;
}

// ---------------------------------------------------------------------------
// Split-K GEMM with FUSED L1-score epilogue.
// C = A @ W (all SMEM, 16 warps, 8x8 thread tiles).  After the split-K
// reduction the kh=0 warps hold final C rows in registers; they compute the
// per-row dot products with satt (a_s / a_d) via 16-lane butterflies and
// write s_s / s_d directly — no separate phase, no sxh re-read.
// One internal __syncthreads(); all 512 threads must call.
// ---------------------------------------------------------------------------
__device__ __forceinline__ void gemm_sk_scores(const float* __restrict__ A,
                                               const float* __restrict__ sW,
                                               float* __restrict__ C,
                                               const float* __restrict__ satt,
                                               float* __restrict__ s_s,
                                               float* __restrict__ s_d,
                                               int tid) {
    const int w  = tid >> 5;
    const int l  = tid & 31;
    const int kh = w >> 3;
    const int r0 = (w & 7) * 16 + (l >> 4) * 8;
    const int ca = (l & 15) * 4;
    const int k0 = kh * 64;

    unsigned long long acc[8][4];
#pragma unroll
    for (int i = 0; i < 8; ++i)
#pragma unroll
        for (int j = 0; j < 4; ++j) acc[i][j] = 0ull;

#pragma unroll 4
    for (int k = k0; k < k0 + 64; k += 2) {
        float2 a[8];
#pragma unroll
        for (int i = 0; i < 8; ++i)
            a[i] = *(const float2*)(A + (r0 + i) * HFEAT + k);
        ulonglong2 w00 = *(const ulonglong2*)(sW + k * HFEAT + ca);
        ulonglong2 w01 = *(const ulonglong2*)(sW + k * HFEAT + ca + 64);
        ulonglong2 w10 = *(const ulonglong2*)(sW + (k + 1) * HFEAT + ca);
        ulonglong2 w11 = *(const ulonglong2*)(sW + (k + 1) * HFEAT + ca + 64);
#pragma unroll
        for (int i = 0; i < 8; ++i) {
            unsigned long long ax = pack2(a[i].x);
            unsigned long long ay = pack2(a[i].y);
            ffma2(acc[i][0], ax, w00.x);
            ffma2(acc[i][1], ax, w00.y);
            ffma2(acc[i][2], ax, w01.x);
            ffma2(acc[i][3], ax, w01.y);
            ffma2(acc[i][0], ay, w10.x);
            ffma2(acc[i][1], ay, w10.y);
            ffma2(acc[i][2], ay, w11.x);
            ffma2(acc[i][3], ay, w11.y);
        }
    }

    if (kh == 1) {
#pragma unroll
        for (int i = 0; i < 8; ++i) {
            ulonglong2 s0, s1;
            s0.x = acc[i][0]; s0.y = acc[i][1];
            s1.x = acc[i][2]; s1.y = acc[i][3];
            *(ulonglong2*)(C + (r0 + i) * HFEAT + ca)      = s0;
            *(ulonglong2*)(C + (r0 + i) * HFEAT + ca + 64) = s1;
        }
    }
    __syncthreads();   // also orders satt restage (done pre-call) before reads below
    if (kh == 0) {
        // attention vector slices for this thread's 8 columns
        float4 a1lo = *(const float4*)(satt + ca);
        float4 a1hi = *(const float4*)(satt + ca + 64);
        float4 a2lo = *(const float4*)(satt + 128 + ca);
        float4 a2hi = *(const float4*)(satt + 128 + ca + 64);
        float ssp[8], ddp[8];
#pragma unroll
        for (int i = 0; i < 8; ++i) {
            ulonglong2 p0 = *(const ulonglong2*)(C + (r0 + i) * HFEAT + ca);
            ulonglong2 p1 = *(const ulonglong2*)(C + (r0 + i) * HFEAT + ca + 64);
            fadd2(acc[i][0], p0.x);
            fadd2(acc[i][1], p0.y);
            fadd2(acc[i][2], p1.x);
            fadd2(acc[i][3], p1.y);
            ulonglong2 s0, s1;
            s0.x = acc[i][0]; s0.y = acc[i][1];
            s1.x = acc[i][2]; s1.y = acc[i][3];
            *(ulonglong2*)(C + (r0 + i) * HFEAT + ca)      = s0;
            *(ulonglong2*)(C + (r0 + i) * HFEAT + ca + 64) = s1;
            float2 c0 = unpk2(acc[i][0]);
            float2 c1 = unpk2(acc[i][1]);
            float2 c2 = unpk2(acc[i][2]);
            float2 c3 = unpk2(acc[i][3]);
            ssp[i] = c0.x*a1lo.x + c0.y*a1lo.y + c1.x*a1lo.z + c1.y*a1lo.w
                   + c2.x*a1hi.x + c2.y*a1hi.y + c3.x*a1hi.z + c3.y*a1hi.w;
            ddp[i] = c0.x*a2lo.x + c0.y*a2lo.y + c1.x*a2lo.z + c1.y*a2lo.w
                   + c2.x*a2hi.x + c2.y*a2hi.y + c3.x*a2hi.z + c3.y*a2hi.w;
        }
        // 16-lane butterfly (stays within half-warp: offsets < 16)
#pragma unroll
        for (int o = 8; o; o >>= 1) {
#pragma unroll
            for (int i = 0; i < 8; ++i) {
                ssp[i] += __shfl_xor_sync(0xffffffffu, ssp[i], o);
                ddp[i] += __shfl_xor_sync(0xffffffffu, ddp[i], o);
            }
        }
        if ((l & 15) == 0) {
#pragma unroll
            for (int i = 0; i < 8; ++i) {
                s_s[r0 + i] = ssp[i];
                s_d[r0 + i] = ddp[i];
            }
        }
    }
}

__global__ __launch_bounds__(NTHREADS, 1)
void gnn_kernel(const float* __restrict__ x,
                const float* __restrict__ g0as, const float* __restrict__ g0ad,
                const float* __restrict__ g0b,
                const float* __restrict__ bn0g, const float* __restrict__ bn0b,
                const float* __restrict__ bn0m, const float* __restrict__ bn0v,
                const float* __restrict__ g1w, const float* __restrict__ g1as,
                const float* __restrict__ g1ad, const float* __restrict__ g1b,
                const float* __restrict__ bn1g, const float* __restrict__ bn1b,
                const float* __restrict__ bn1m, const float* __restrict__ bn1v,
                const float* __restrict__ w1, const float* __restrict__ b1,
                const float* __restrict__ w2, const float* __restrict__ b2,
                float* __restrict__ out) {
    extern __shared__ float smem[];
    float* sh    = smem + OFF_SH;     // L0 output; later: pool partials
    float* sxh   = smem + OFF_SXH;
    float* sW    = smem + OFF_SW;
    float* sex   = smem + OFF_SEX;
    float* s_s   = smem + OFF_SS;
    float* s_d   = smem + OFF_SD;
    float* satt  = smem + OFF_SATT;
    float* sscale= smem + OFF_SCALE;
    float* sbias = smem + OFF_BIAS;
    float* hp    = smem + OFF_HP;
    float* zz    = smem + OFF_ZZ;
    float* sxv   = smem + OFF_XV;
    float* st    = smem + OFF_ST;
    int*   sptr  = (int*)(smem + SM_FLOATS);
    int*   scsr  = sptr + 132;
    int*   sdord = scsr + ETOT;

    const int tid  = threadIdx.x;
    const int wid  = tid >> 5;
    const int lane = tid & 31;
    const int b    = blockIdx.x;
    const unsigned mbar = (unsigned)__cvta_generic_to_shared(smem + OFF_MBAR);

    // ---- init ----
    if (tid == 0)
        asm volatile("mbarrier.init.shared.b64 [%0], %1;" :: "r"(mbar), "r"(1) : "memory");
    if (tid < 128) {
        satt[tid]       = g0as[tid];
        satt[128 + tid] = g0ad[tid];
        float sc = bn0g[tid] * rsqrtf(bn0v[tid] + 1e-5f);
        sscale[tid] = sc;
        sbias[tid]  = fmaf(g0b[tid] - bn0m[tid], sc, bn0b[tid]);
        sxv[tid]   = x[b * NNODE + tid];
        st[tid]    = g_t[tid];
        sdord[tid] = g_sord[tid];
    }
    __syncthreads();

    // async loads: CSR (ptr+src) + W1; land before the L0 softmax wait
    if (tid == 0) {
        unsigned a_sw   = (unsigned)__cvta_generic_to_shared(sW);
        unsigned a_sptr = (unsigned)__cvta_generic_to_shared(sptr);
        unsigned a_scsr = (unsigned)__cvta_generic_to_shared(scsr);
        asm volatile("mbarrier.arrive.expect_tx.shared.b64 _, [%0], %1;"
                     :: "r"(mbar), "r"(TX_BYTES) : "memory");
        asm volatile("cp.async.bulk.shared::cta.global.mbarrier::complete_tx::bytes "
                     "[%0], [%1], %2, [%3];"
                     :: "r"(a_sw), "l"(g1w), "r"(HFEAT * HFEAT * 4), "r"(mbar) : "memory");
        asm volatile("cp.async.bulk.shared::cta.global.mbarrier::complete_tx::bytes "
                     "[%0], [%1], %2, [%3];"
                     :: "r"(a_sptr), "l"(g_csr_ptr), "r"(132 * 4), "r"(mbar) : "memory");
        asm volatile("cp.async.bulk.shared::cta.global.mbarrier::complete_tx::bytes "
                     "[%0], [%1], %2, [%3];"
                     :: "r"(a_scsr), "l"(g_csr_src), "r"(ETOT * 4), "r"(mbar) : "memory");
    }

    // ---- xh0 = x*A_j + B_j (PWL) with fused L0 scores, batch-4 prefetch ----
    {
        float4 a1 = *(const float4*)(satt + lane * 4);
        float4 a2 = *(const float4*)(satt + 128 + lane * 4);
        const int l4 = lane * 4;
#pragma unroll
        for (int base = 0; base < 8; base += 4) {
            float xvv[4];
            float4 Av[4], Bv[4];
#pragma unroll
            for (int q = 0; q < 4; ++q) {           // issue all 8 loads (MLP=8)
                int n = wid + ((base + q) << 4);
                float xv = sxv[n];
                xvv[q] = xv;
                int j = 0;
#pragma unroll
                for (int r = 0; r < 4; ++r)
                    j += __popc(__ballot_sync(0xffffffffu, st[lane + 32 * r] <= xv));
                Av[q] = *(const float4*)(g_A + j * HFEAT + l4);
                Bv[q] = *(const float4*)(g_B + j * HFEAT + l4);
            }
#pragma unroll
            for (int q = 0; q < 4; ++q) {
                int n = wid + ((base + q) << 4);
                float xv = xvv[q];
                float4 v;
                v.x = fmaf(xv, Av[q].x, Bv[q].x);
                v.y = fmaf(xv, Av[q].y, Bv[q].y);
                v.z = fmaf(xv, Av[q].z, Bv[q].z);
                v.w = fmaf(xv, Av[q].w, Bv[q].w);
                *(float4*)(sxh + n * HFEAT + l4) = v;
                float ss = v.x*a1.x + v.y*a1.y + v.z*a1.z + v.w*a1.w;
                float dd = v.x*a2.x + v.y*a2.y + v.z*a2.z + v.w*a2.w;
#pragma unroll
                for (int o = 4; o; o >>= 1) {
                    ss += __shfl_xor_sync(0xffffffffu, ss, o);
                    dd += __shfl_xor_sync(0xffffffffu, dd, o);
                }
                if ((lane & 7) == 0) {
                    s_s[n * 4 + (lane >> 3)] = ss;
                    s_d[n * 4 + (lane >> 3)] = dd;
                }
            }
        }
    }
    __syncthreads();

    // wait for async CSR + W1 (all threads)
    asm volatile(
        "{\n\t"
        ".reg .pred P1;\n\t"
        "W_%=:\n\t"
        "mbarrier.try_wait.parity.acquire.cta.shared::cta.b64 P1, [%0], 0, 0x989680;\n\t"
        "@P1 bra D_%=;\n\t"
        "bra W_%=;\n\t"
        "D_%=:\n\t"
        "}" :: "r"(mbar) : "memory");

    // ---- L0 fused single-pass softmax + aggregate + BN0 + relu ----
    {
        const int hh = lane >> 3;
        const int pi = lane & 7;
        const int l4 = lane * 4;
        float4 sc = *(const float4*)(sscale + l4);
        float4 bs = *(const float4*)(sbias + l4);
#pragma unroll
        for (int it = 0; it < 8; ++it) {
            const int d = sdord[(it << 4) + wid];   // degree-balanced order
            const int beg = sptr[d], end = sptr[d + 1];
            const float sd = s_d[d * 4 + hh];
            float sum = 0.0f;
            for (int p = beg + pi; p < end; p += 8) {
                float e = s_s[(scsr[p] << 2) + hh] + sd;
                e = (e > 0.0f) ? e : 0.2f * e;
                float ex = __expf(e);        // softmax shift-invariant; |e| small
                sex[(p << 2) + hh] = ex;
                sum += ex;
            }
#pragma unroll
            for (int o = 4; o; o >>= 1)
                sum += __shfl_xor_sync(0xffffffffu, sum, o);
            const float rv = 1.0f / sum;

            float4 acc = make_float4(0.f, 0.f, 0.f, 0.f);
            int p = beg;
            float wv = sex[(p << 2) + hh];
            float4 v = *(const float4*)(sxh + (scsr[p] << 7) + l4);
            for (++p; p < end; ++p) {
                float wn = sex[(p << 2) + hh];
                float4 vn = *(const float4*)(sxh + (scsr[p] << 7) + l4);
                acc.x = fmaf(wv, v.x, acc.x);
                acc.y = fmaf(wv, v.y, acc.y);
                acc.z = fmaf(wv, v.z, acc.z);
                acc.w = fmaf(wv, v.w, acc.w);
                wv = wn; v = vn;
            }
            acc.x = fmaf(wv, v.x, acc.x);
            acc.y = fmaf(wv, v.y, acc.y);
            acc.z = fmaf(wv, v.z, acc.z);
            acc.w = fmaf(wv, v.w, acc.w);

            float4 r;
            r.x = fmaxf(fmaf(acc.x * rv, sc.x, bs.x), 0.0f);
            r.y = fmaxf(fmaf(acc.y * rv, sc.y, bs.y), 0.0f);
            r.z = fmaxf(fmaf(acc.z * rv, sc.z, bs.z), 0.0f);
            r.w = fmaxf(fmaf(acc.w * rv, sc.w, bs.w), 0.0f);
            *(float4*)(sh + d * HFEAT + l4) = r;
        }
    }
    __syncthreads();

    // restage L1 attention + BN1 fold (reads ordered by gemm's internal barrier)
    if (tid < 128) {
        float sc = bn1g[tid] * rsqrtf(bn1v[tid] + 1e-5f);
        sscale[tid] = sc;
        sbias[tid]  = fmaf(g1b[tid] - bn1m[tid], sc, bn1b[tid]);
        satt[tid]       = g1as[tid];
        satt[128 + tid] = g1ad[tid];
    }

    // ===== GAT layer 1 GEMM with fused score epilogue (writes s_s/s_d) =====
    gemm_sk_scores(sh, sW, sxh, satt, s_s, s_d, tid);
    __syncthreads();

    // ---- L1 fused single-pass softmax + aggregate + BN1 + relu + POOL ----
    {
        const int l4 = lane * 4;
        float4 sc = *(const float4*)(sscale + l4);
        float4 bs = *(const float4*)(sbias + l4);
        float4 pacc = make_float4(0.f, 0.f, 0.f, 0.f);
#pragma unroll
        for (int it = 0; it < 8; ++it) {
            const int d = sdord[(it << 4) + wid];   // degree-balanced order
            const int beg = sptr[d], end = sptr[d + 1];
            const float sd = s_d[d];
            float sum = 0.0f;
            for (int p = beg + lane; p < end; p += 32) {
                float e = s_s[scsr[p]] + sd;
                e = (e > 0.0f) ? e : 0.2f * e;
                float ex = __expf(e);
                sex[p] = ex;
                sum += ex;
            }
#pragma unroll
            for (int o = 16; o; o >>= 1)
                sum += __shfl_xor_sync(0xffffffffu, sum, o);
            const float rv = 1.0f / sum;

            float4 acc = make_float4(0.f, 0.f, 0.f, 0.f);
            int p = beg;
            float wv = sex[p];
            float4 v = *(const float4*)(sxh + (scsr[p] << 7) + l4);
            for (++p; p < end; ++p) {
                float wn = sex[p];
                float4 vn = *(const float4*)(sxh + (scsr[p] << 7) + l4);
                acc.x = fmaf(wv, v.x, acc.x);
                acc.y = fmaf(wv, v.y, acc.y);
                acc.z = fmaf(wv, v.z, acc.z);
                acc.w = fmaf(wv, v.w, acc.w);
                wv = wn; v = vn;
            }
            acc.x = fmaf(wv, v.x, acc.x);
            acc.y = fmaf(wv, v.y, acc.y);
            acc.z = fmaf(wv, v.z, acc.z);
            acc.w = fmaf(wv, v.w, acc.w);

            pacc.x += fmaxf(fmaf(acc.x * rv, sc.x, bs.x), 0.0f);
            pacc.y += fmaxf(fmaf(acc.y * rv, sc.y, bs.y), 0.0f);
            pacc.z += fmaxf(fmaf(acc.z * rv, sc.z, bs.z), 0.0f);
            pacc.w += fmaxf(fmaf(acc.w * rv, sc.w, bs.w), 0.0f);
        }
        *(float4*)(sh + wid * HFEAT + l4) = pacc;   // per-warp pool partial
    }
    __syncthreads();

    // ---- pool reduce ----
    if (tid < 128) {
        float acc = 0.0f;
#pragma unroll
        for (int w = 0; w < 16; ++w) acc += sh[w * HFEAT + tid];
        hp[tid] = acc * (1.0f / 128.0f);
    }
    __syncthreads();

    // ---- MLP ----
    if (tid < 64) {
        float acc = b1[tid];
#pragma unroll 8
        for (int f = 0; f < 128; ++f) acc = fmaf(hp[f], w1[f * 64 + tid], acc);
        zz[tid] = fmaxf(acc, 0.0f);
    }
    __syncthreads();
    if (tid == 0) {
        float acc = b2[0];
#pragma unroll
        for (int j = 0; j < 64; ++j) acc = fmaf(zz[j], w2[j], acc);
        out[b] = acc;
    }
}

// ---------------------------------------------------------------------------
extern "C" void kernel_launch(void* const* d_in, const int* in_sizes, int n_in,
                              void* d_out, int out_size) {
    (void)in_sizes; (void)n_in; (void)out_size;
    const float* x    = (const float*)d_in[0];
    const int*   ei   = (const int*)d_in[1];
    const float* w_in = (const float*)d_in[2];
    const float* b_in = (const float*)d_in[3];
    const float* g0w  = (const float*)d_in[4];
    const float* g0as = (const float*)d_in[5];
    const float* g0ad = (const float*)d_in[6];
    const float* g0b  = (const float*)d_in[7];
    const float* bn0g = (const float*)d_in[8];
    const float* bn0b = (const float*)d_in[9];
    const float* bn0m = (const float*)d_in[10];
    const float* bn0v = (const float*)d_in[11];
    const float* g1w  = (const float*)d_in[12];
    const float* g1as = (const float*)d_in[13];
    const float* g1ad = (const float*)d_in[14];
    const float* g1b  = (const float*)d_in[15];
    const float* bn1g = (const float*)d_in[16];
    const float* bn1b = (const float*)d_in[17];
    const float* bn1m = (const float*)d_in[18];
    const float* bn1v = (const float*)d_in[19];
    const float* w1   = (const float*)d_in[20];
    const float* b1   = (const float*)d_in[21];
    const float* w2   = (const float*)d_in[22];
    const float* b2   = (const float*)d_in[23];
    float* out = (float*)d_out;

    cudaFuncSetAttribute(gnn_kernel,
                         cudaFuncAttributeMaxDynamicSharedMemorySize, SMEM_BYTES);

    setup_kernel<<<2, 1024>>>(ei, w_in, b_in, g0w);
    gnn_kernel<<<NGRAPH, NTHREADS, SMEM_BYTES>>>(
        x, g0as, g0ad, g0b, bn0g, bn0b, bn0m, bn0v,
        g1w, g1as, g1ad, g1b, bn1g, bn1b, bn1m, bn1v,
        w1, b1, w2, b2, out);
}